// round 7
// baseline (speedup 1.0000x reference)
#include <cuda_runtime.h>
#include <cuda_bf16.h>
#include <math.h>
#include <stdint.h>

#define B_   2
#define S_   2048
#define H_   3072
#define NH   32
#define NKV  8
#define HD   96
#define QKV_W (NH*HD + 2*NKV*HD)   // 4608
#define M_   (B_*S_)               // 4096

// ---------------- scratch (device globals: allocation-free rule) -----------
__device__ float g_qkv[(size_t)M_ * QKV_W];
__device__ __nv_bfloat16 g_h_hi[(size_t)M_ * H_],     g_h_lo[(size_t)M_ * H_];
__device__ __nv_bfloat16 g_wq_hi[(size_t)QKV_W * H_], g_wq_lo[(size_t)QKV_W * H_];
__device__ __nv_bfloat16 g_wo_hi[(size_t)H_ * H_],    g_wo_lo[(size_t)H_ * H_];
__device__ __nv_bfloat16 g_a_hi[(size_t)M_ * H_],     g_a_lo[(size_t)M_ * H_];
__device__ __nv_bfloat16 g_q_hi[(size_t)B_*NH*S_*HD],  g_q_lo[(size_t)B_*NH*S_*HD];
__device__ __nv_bfloat16 g_k_hi[(size_t)B_*NKV*S_*HD], g_k_lo[(size_t)B_*NKV*S_*HD];
__device__ __nv_bfloat16 g_v_hi[(size_t)B_*NKV*S_*HD], g_v_lo[(size_t)B_*NKV*S_*HD];

// ---------------- base-target PTX helpers ----------------------------------
__device__ __forceinline__ void cp_async16(uint32_t dst, const void* src) {
    asm volatile("cp.async.cg.shared.global [%0], [%1], 16;"
                 :: "r"(dst), "l"(src) : "memory");
}
#define CP_COMMIT() asm volatile("cp.async.commit_group;" ::: "memory")
#define CP_WAIT(n)  asm volatile("cp.async.wait_group %0;" :: "n"(n) : "memory")

__device__ __forceinline__ void ldsm4(uint32_t& r0, uint32_t& r1, uint32_t& r2,
                                      uint32_t& r3, uint32_t addr) {
    asm volatile("ldmatrix.sync.aligned.m8n8.x4.shared.b16 {%0,%1,%2,%3}, [%4];"
                 : "=r"(r0), "=r"(r1), "=r"(r2), "=r"(r3) : "r"(addr));
}
__device__ __forceinline__ void ldsm4t(uint32_t& r0, uint32_t& r1, uint32_t& r2,
                                       uint32_t& r3, uint32_t addr) {
    asm volatile("ldmatrix.sync.aligned.m8n8.x4.trans.shared.b16 {%0,%1,%2,%3}, [%4];"
                 : "=r"(r0), "=r"(r1), "=r"(r2), "=r"(r3) : "r"(addr));
}
__device__ __forceinline__ void mma16816(float* c, uint32_t a0, uint32_t a1,
                                         uint32_t a2, uint32_t a3,
                                         uint32_t b0, uint32_t b1) {
    asm volatile(
        "mma.sync.aligned.m16n8k16.row.col.f32.bf16.bf16.f32 "
        "{%0,%1,%2,%3}, {%4,%5,%6,%7}, {%8,%9}, {%0,%1,%2,%3};"
        : "+f"(c[0]), "+f"(c[1]), "+f"(c[2]), "+f"(c[3])
        : "r"(a0), "r"(a1), "r"(a2), "r"(a3), "r"(b0), "r"(b1));
}

__device__ __forceinline__ uint32_t pack_bf16x2(float lo, float hi) {
    __nv_bfloat162 p = __floats2bfloat162_rn(lo, hi);
    return *(uint32_t*)&p;
}

// ---------------------------------------------------------------------------
// fp32 -> (bf16 hi, bf16 lo) split
// ---------------------------------------------------------------------------
__global__ void split_f32(const float* __restrict__ x,
                          __nv_bfloat16* __restrict__ hi,
                          __nv_bfloat16* __restrict__ lo, int n4)
{
    int i = blockIdx.x * blockDim.x + threadIdx.x;
    if (i >= n4) return;
    float4 v = ((const float4*)x)[i];
    __nv_bfloat16 h0 = __float2bfloat16_rn(v.x);
    __nv_bfloat16 h1 = __float2bfloat16_rn(v.y);
    __nv_bfloat16 h2 = __float2bfloat16_rn(v.z);
    __nv_bfloat16 h3 = __float2bfloat16_rn(v.w);
    __nv_bfloat16 l0 = __float2bfloat16_rn(v.x - __bfloat162float(h0));
    __nv_bfloat16 l1 = __float2bfloat16_rn(v.y - __bfloat162float(h1));
    __nv_bfloat16 l2 = __float2bfloat16_rn(v.z - __bfloat162float(h2));
    __nv_bfloat16 l3 = __float2bfloat16_rn(v.w - __bfloat162float(h3));
    ((__nv_bfloat162*)hi)[2*i]   = __nv_bfloat162(h0, h1);
    ((__nv_bfloat162*)hi)[2*i+1] = __nv_bfloat162(h2, h3);
    ((__nv_bfloat162*)lo)[2*i]   = __nv_bfloat162(l0, l1);
    ((__nv_bfloat162*)lo)[2*i+1] = __nv_bfloat162(l2, l3);
}

// ---------------------------------------------------------------------------
// 3xBF16 mma.sync GEMM (NT), 128x128 CTA tile, BK=32, 2-stage, 2 CTAs/SM.
// (unchanged from round 6 WIN)
// ---------------------------------------------------------------------------
#define BK      32
#define LDS_    40
#define PLANE_B (128 * LDS_ * 2)
#define BUF_B   (4 * PLANE_B)         // 40960
#define GEMM_SMEM (2 * BUF_B)         // 81920

__global__ __launch_bounds__(256, 2) void gemm_3xbf16(
    const __nv_bfloat16* __restrict__ Ahi, const __nv_bfloat16* __restrict__ Alo,
    const __nv_bfloat16* __restrict__ Bhi, const __nv_bfloat16* __restrict__ Blo,
    float* __restrict__ C, int N, int K)
{
    extern __shared__ __align__(128) char smc[];
    const uint32_t sbase = (uint32_t)__cvta_generic_to_shared(smc);
    const int tid  = threadIdx.x;
    const int warp = tid >> 5, lane = tid & 31;
    const int bm = blockIdx.y * 128, bn = blockIdx.x * 128;
    const int wm = (warp >> 2) * 64;
    const int wn = (warp & 3) * 32;

    const __nv_bfloat16* srcs[4] = {
        Ahi + (size_t)bm * K, Alo + (size_t)bm * K,
        Bhi + (size_t)bn * K, Blo + (size_t)bn * K };

    const int nch = K / BK;

    auto load_chunk = [&](int kc, int bb) {
        uint32_t sb = sbase + bb * BUF_B;
        #pragma unroll
        for (int p = 0; p < 4; p++) {
            const __nv_bfloat16* sp = srcs[p] + kc * BK;
            uint32_t pb = sb + p * PLANE_B;
            #pragma unroll
            for (int t = 0; t < 2; t++) {
                int f = tid + t * 256;
                int r = f >> 2, j = f & 3;
                cp_async16(pb + r * (LDS_ * 2) + j * 16,
                           sp + (size_t)r * K + j * 8);
            }
        }
        CP_COMMIT();
    };

    float c[4][4][4];
    #pragma unroll
    for (int i = 0; i < 4; i++)
        #pragma unroll
        for (int j = 0; j < 4; j++)
            #pragma unroll
            for (int q = 0; q < 4; q++) c[i][j][q] = 0.f;

    load_chunk(0, 0);

    const int arow = lane & 15;
    const int ak8  = (lane >> 4) * 8;
    const int brow = (lane & 7) + ((lane >> 4) << 3);
    const int bk8  = ((lane >> 3) & 1) * 8;

    #pragma unroll 1
    for (int kc = 0; kc < nch; kc++) {
        const int bb = kc & 1;
        CP_WAIT(0);
        __syncthreads();
        if (kc + 1 < nch) load_chunk(kc + 1, bb ^ 1);

        const uint32_t sAh = sbase + bb * BUF_B;
        const uint32_t sAl = sAh + PLANE_B;
        const uint32_t sBh = sAh + 2 * PLANE_B;
        const uint32_t sBl = sAh + 3 * PLANE_B;

        #pragma unroll
        for (int ks = 0; ks < 2; ks++) {
            const int k0 = ks * 16;
            uint32_t bh[4][2], bl[4][2];
            #pragma unroll
            for (int tp = 0; tp < 2; tp++) {
                uint32_t off = (uint32_t)((wn + tp*16 + brow) * LDS_ + k0 + bk8) * 2;
                ldsm4(bh[tp*2][0], bh[tp*2][1], bh[tp*2+1][0], bh[tp*2+1][1], sBh + off);
                ldsm4(bl[tp*2][0], bl[tp*2][1], bl[tp*2+1][0], bl[tp*2+1][1], sBl + off);
            }
            #pragma unroll
            for (int ti = 0; ti < 4; ti++) {
                uint32_t off = (uint32_t)((wm + ti*16 + arow) * LDS_ + k0 + ak8) * 2;
                uint32_t ah[4], al[4];
                ldsm4(ah[0], ah[1], ah[2], ah[3], sAh + off);
                ldsm4(al[0], al[1], al[2], al[3], sAl + off);
                #pragma unroll
                for (int tj = 0; tj < 4; tj++) {
                    mma16816(c[ti][tj], ah[0], ah[1], ah[2], ah[3],
                             bh[tj][0], bh[tj][1]);
                    mma16816(c[ti][tj], ah[0], ah[1], ah[2], ah[3],
                             bl[tj][0], bl[tj][1]);
                    mma16816(c[ti][tj], al[0], al[1], al[2], al[3],
                             bh[tj][0], bh[tj][1]);
                }
            }
        }
    }

    const int cr = lane >> 2, cc = (lane & 3) * 2;
    #pragma unroll
    for (int ti = 0; ti < 4; ti++) {
        #pragma unroll
        for (int tj = 0; tj < 4; tj++) {
            int r0 = bm + wm + ti*16 + cr;
            int col = bn + wn + tj*8 + cc;
            *(float2*)(C + (size_t)r0 * N + col)       = make_float2(c[ti][tj][0], c[ti][tj][1]);
            *(float2*)(C + (size_t)(r0 + 8) * N + col) = make_float2(c[ti][tj][2], c[ti][tj][3]);
        }
    }
}

// ---------------------------------------------------------------------------
// RoPE + hi/lo split into head-major planes. Q gets softmax scale folded in.
// ---------------------------------------------------------------------------
__global__ void rope_split(const float* __restrict__ qkv,
                           __nv_bfloat16* __restrict__ qhi, __nv_bfloat16* __restrict__ qlo,
                           __nv_bfloat16* __restrict__ khi, __nv_bfloat16* __restrict__ klo)
{
    const int total = B_ * S_ * (NH + NKV) * (HD / 2);
    int i = blockIdx.x * blockDim.x + threadIdx.x;
    if (i >= total) return;
    int d    = i % (HD/2);
    int t    = i / (HD/2);
    int head = t % (NH + NKV);
    int bs   = t / (NH + NKV);
    int b    = bs / S_;
    int s    = bs % S_;

    float inv = expf(-(float)d * (logf(10000.0f) / 48.0f));
    float ang = (float)s * inv;
    float sn, cs;
    sincosf(ang, &sn, &cs);

    const float* base = qkv + (size_t)bs * QKV_W + head * HD;
    float x1 = base[d];
    float x2 = base[d + 48];
    float y1 = x1 * cs - x2 * sn;
    float y2 = x2 * cs + x1 * sn;

    __nv_bfloat16 *hi, *lo;
    size_t idx;
    if (head < NH) {
        const float scale = 0.10206207261596577f;
        y1 *= scale; y2 *= scale;
        idx = ((size_t)(b * NH + head) * S_ + s) * HD;
        hi = qhi; lo = qlo;
    } else {
        idx = ((size_t)(b * NKV + (head - NH)) * S_ + s) * HD;
        hi = khi; lo = klo;
    }
    __nv_bfloat16 h1 = __float2bfloat16_rn(y1);
    __nv_bfloat16 h2 = __float2bfloat16_rn(y2);
    hi[idx + d]      = h1;
    hi[idx + d + 48] = h2;
    lo[idx + d]      = __float2bfloat16_rn(y1 - __bfloat162float(h1));
    lo[idx + d + 48] = __float2bfloat16_rn(y2 - __bfloat162float(h2));
}

__global__ void v_split(const float* __restrict__ qkv,
                        __nv_bfloat16* __restrict__ vhi, __nv_bfloat16* __restrict__ vlo)
{
    const int total = B_ * S_ * NKV * (HD / 4);
    int i = blockIdx.x * blockDim.x + threadIdx.x;
    if (i >= total) return;
    int d4  = i % (HD/4);
    int t   = i / (HD/4);
    int kvh = t % NKV;
    int bs  = t / NKV;
    int b   = bs / S_;
    int s   = bs % S_;

    const float* src = qkv + (size_t)bs * QKV_W + NH*HD + NKV*HD + kvh*HD + d4*4;
    float4 v = *(const float4*)src;
    size_t idx = ((size_t)(b * NKV + kvh) * S_ + s) * HD + d4*4;
    __nv_bfloat16 h0 = __float2bfloat16_rn(v.x);
    __nv_bfloat16 h1 = __float2bfloat16_rn(v.y);
    __nv_bfloat16 h2 = __float2bfloat16_rn(v.z);
    __nv_bfloat16 h3 = __float2bfloat16_rn(v.w);
    *(__nv_bfloat162*)(vhi + idx)     = __nv_bfloat162(h0, h1);
    *(__nv_bfloat162*)(vhi + idx + 2) = __nv_bfloat162(h2, h3);
    *(__nv_bfloat162*)(vlo + idx) =
        __nv_bfloat162(__float2bfloat16_rn(v.x - __bfloat162float(h0)),
                       __float2bfloat16_rn(v.y - __bfloat162float(h1)));
    *(__nv_bfloat162*)(vlo + idx + 2) =
        __nv_bfloat162(__float2bfloat16_rn(v.z - __bfloat162float(h2)),
                       __float2bfloat16_rn(v.w - __bfloat162float(h3)));
}

// ---------------------------------------------------------------------------
// Flash attention on mma.sync (3xBF16). CTA: 64 queries x one (b,h),
// 128 threads (4 warps x 16 rows), 32-key tiles, 3-stage KV ring.
// smem 106496 -> 2 CTAs/SM so softmax of one CTA overlaps mma of the other.
// Heaviest q-tiles launched first (reversed blockIdx).
// ---------------------------------------------------------------------------
#define ALDS   104
#define BLKQ   64
#define KT     32
#define QBYTES (BLKQ * ALDS * 2)        // 13312
#define KVTILE (KT * ALDS * 2)          // 6656
#define KVBUF  (4 * KVTILE)             // 26624
#define ASTAGES 3
#define ATT_SMEM (2*QBYTES + ASTAGES*KVBUF)   // 106496

__global__ __launch_bounds__(128, 2) void attn_mma(
    const __nv_bfloat16* __restrict__ qhi, const __nv_bfloat16* __restrict__ qlo,
    const __nv_bfloat16* __restrict__ khi, const __nv_bfloat16* __restrict__ klo,
    const __nv_bfloat16* __restrict__ vhi, const __nv_bfloat16* __restrict__ vlo,
    __nv_bfloat16* __restrict__ ahi, __nv_bfloat16* __restrict__ alo)
{
    extern __shared__ __align__(128) char smc[];
    const uint32_t sb  = (uint32_t)__cvta_generic_to_shared(smc);
    const uint32_t sQh = sb, sQl = sb + QBYTES;
    const uint32_t sKV = sb + 2 * QBYTES;

    const int tid  = threadIdx.x;
    const int warp = tid >> 5, lane = tid & 31;
    const int qi = (S_/BLKQ - 1) - blockIdx.x;   // reversed: heavy tiles first
    const int bh = blockIdx.y;
    const int b  = bh >> 5, h = bh & 31, kvh = h >> 2;
    const int q0 = qi * BLKQ;
    const int wm = warp * 16;

    const __nv_bfloat16* qsh = qhi + ((size_t)(b*NH + h) * S_ + q0) * HD;
    const __nv_bfloat16* qsl = qlo + ((size_t)(b*NH + h) * S_ + q0) * HD;
    const __nv_bfloat16* ksh = khi + (size_t)(b*NKV + kvh) * S_ * HD;
    const __nv_bfloat16* ksl = klo + (size_t)(b*NKV + kvh) * S_ * HD;
    const __nv_bfloat16* vsh = vhi + (size_t)(b*NKV + kvh) * S_ * HD;
    const __nv_bfloat16* vsl = vlo + (size_t)(b*NKV + kvh) * S_ * HD;

    // Q tile: 64 rows x 12 16B chunks x 2 planes = 1536 cp.asyncs, 12/thread
    #pragma unroll
    for (int u = 0; u < 6; u++) {
        int f = tid + u * 128;            // 0..767
        int r = f / 12, cidx = f % 12;
        cp_async16(sQh + r * (ALDS*2) + cidx * 16, qsh + (size_t)r * HD + cidx * 8);
        cp_async16(sQl + r * (ALDS*2) + cidx * 16, qsl + (size_t)r * HD + cidx * 8);
    }

    auto load_kv = [&](int kt, int bb) {
        uint32_t base = sKV + bb * KVBUF;
        int k0 = kt * KT;
        #pragma unroll
        for (int u = 0; u < 3; u++) {
            int f = tid + u * 128;        // 0..383
            int r = f / 12, cidx = f % 12;
            size_t g = (size_t)(k0 + r) * HD + cidx * 8;
            uint32_t o = r * (ALDS*2) + cidx * 16;
            cp_async16(base + 0*KVTILE + o, ksh + g);
            cp_async16(base + 1*KVTILE + o, ksl + g);
            cp_async16(base + 2*KVTILE + o, vsh + g);
            cp_async16(base + 3*KVTILE + o, vsl + g);
        }
        CP_COMMIT();
    };

    const int nkt = (q0 + BLKQ) / KT;     // 2*qi + 2
    load_kv(0, 0);                        // group 0 also covers Q loads
    load_kv(1, 1);                        // nkt >= 2 always

    const int arow = lane & 15;
    const int ak8  = (lane >> 4) * 8;
    const int brow = (lane & 7) + ((lane >> 4) << 3);
    const int bk8  = ((lane >> 3) & 1) * 8;
    const int vrow = lane & 15;
    const int vn8  = (lane >> 4) * 8;
    const int r_   = lane >> 2;
    const int c2_  = (lane & 3) * 2;

    float o[12][4];
    #pragma unroll
    for (int t = 0; t < 12; t++)
        #pragma unroll
        for (int q = 0; q < 4; q++) o[t][q] = 0.f;
    float m0 = -1e30f, m1 = -1e30f, l0 = 0.f, l1 = 0.f;

    const int row_g0 = q0 + wm + r_;
    const int wmax   = q0 + wm + 15;

    int bb = 0;
    #pragma unroll 1
    for (int kt = 0; kt < nkt; kt++) {
        const int k0 = kt * KT;
        CP_WAIT(1);
        __syncthreads();
        if (kt + 2 < nkt) {
            int nb = bb + 2; if (nb >= ASTAGES) nb -= ASTAGES;
            load_kv(kt + 2, nb);
        } else CP_COMMIT();

        if (k0 <= wmax) {
            const uint32_t sKh = sKV + bb * KVBUF;
            const uint32_t sKl = sKh + KVTILE;
            const uint32_t sVh = sKh + 2 * KVTILE;
            const uint32_t sVl = sKh + 3 * KVTILE;

            // ---- scores: 32 keys = 4 n8 tiles ----
            float s[4][4];
            #pragma unroll
            for (int t = 0; t < 4; t++)
                #pragma unroll
                for (int q = 0; q < 4; q++) s[t][q] = 0.f;

            #pragma unroll
            for (int ks = 0; ks < 6; ks++) {
                uint32_t aoff = (uint32_t)((wm + arow) * ALDS + ks*16 + ak8) * 2;
                uint32_t ah[4], al[4];
                ldsm4(ah[0], ah[1], ah[2], ah[3], sQh + aoff);
                ldsm4(al[0], al[1], al[2], al[3], sQl + aoff);
                #pragma unroll
                for (int np = 0; np < 2; np++) {
                    uint32_t boff = (uint32_t)((np*16 + brow) * ALDS + ks*16 + bk8) * 2;
                    uint32_t bh_[4], bl_[4];
                    ldsm4(bh_[0], bh_[1], bh_[2], bh_[3], sKh + boff);
                    ldsm4(bl_[0], bl_[1], bl_[2], bl_[3], sKl + boff);
                    mma16816(s[2*np],   ah[0],ah[1],ah[2],ah[3], bh_[0], bh_[1]);
                    mma16816(s[2*np],   ah[0],ah[1],ah[2],ah[3], bl_[0], bl_[1]);
                    mma16816(s[2*np],   al[0],al[1],al[2],al[3], bh_[0], bh_[1]);
                    mma16816(s[2*np+1], ah[0],ah[1],ah[2],ah[3], bh_[2], bh_[3]);
                    mma16816(s[2*np+1], ah[0],ah[1],ah[2],ah[3], bl_[2], bl_[3]);
                    mma16816(s[2*np+1], al[0],al[1],al[2],al[3], bh_[2], bh_[3]);
                }
            }

            // ---- causal mask ----
            if (k0 + KT - 1 > q0 + wm) {
                #pragma unroll
                for (int t = 0; t < 4; t++) {
                    int col = k0 + t*8 + c2_;
                    if (col     > row_g0)     s[t][0] = -1e30f;
                    if (col + 1 > row_g0)     s[t][1] = -1e30f;
                    if (col     > row_g0 + 8) s[t][2] = -1e30f;
                    if (col + 1 > row_g0 + 8) s[t][3] = -1e30f;
                }
            }

            // ---- online softmax ----
            float mx0 = -1e30f, mx1 = -1e30f;
            #pragma unroll
            for (int t = 0; t < 4; t++) {
                mx0 = fmaxf(mx0, fmaxf(s[t][0], s[t][1]));
                mx1 = fmaxf(mx1, fmaxf(s[t][2], s[t][3]));
            }
            mx0 = fmaxf(mx0, __shfl_xor_sync(0xffffffff, mx0, 1));
            mx0 = fmaxf(mx0, __shfl_xor_sync(0xffffffff, mx0, 2));
            mx1 = fmaxf(mx1, __shfl_xor_sync(0xffffffff, mx1, 1));
            mx1 = fmaxf(mx1, __shfl_xor_sync(0xffffffff, mx1, 2));

            float mn0 = fmaxf(m0, mx0), mn1 = fmaxf(m1, mx1);
            float al0 = __expf(m0 - mn0), al1 = __expf(m1 - mn1);
            m0 = mn0; m1 = mn1;

            float sum0 = 0.f, sum1 = 0.f;
            #pragma unroll
            for (int t = 0; t < 4; t++) {
                s[t][0] = __expf(s[t][0] - m0);
                s[t][1] = __expf(s[t][1] - m0);
                s[t][2] = __expf(s[t][2] - m1);
                s[t][3] = __expf(s[t][3] - m1);
                sum0 += s[t][0] + s[t][1];
                sum1 += s[t][2] + s[t][3];
            }
            sum0 += __shfl_xor_sync(0xffffffff, sum0, 1);
            sum0 += __shfl_xor_sync(0xffffffff, sum0, 2);
            sum1 += __shfl_xor_sync(0xffffffff, sum1, 1);
            sum1 += __shfl_xor_sync(0xffffffff, sum1, 2);
            l0 = l0 * al0 + sum0;
            l1 = l1 * al1 + sum1;

            #pragma unroll
            for (int t = 0; t < 12; t++) {
                o[t][0] *= al0; o[t][1] *= al0;
                o[t][2] *= al1; o[t][3] *= al1;
            }

            // ---- O += P V ----
            #pragma unroll
            for (int ks = 0; ks < 2; ks++) {
                const int j0 = 2*ks, j1 = 2*ks + 1;
                uint32_t ph[4], pl[4];
                ph[0] = pack_bf16x2(s[j0][0], s[j0][1]);
                ph[1] = pack_bf16x2(s[j0][2], s[j0][3]);
                ph[2] = pack_bf16x2(s[j1][0], s[j1][1]);
                ph[3] = pack_bf16x2(s[j1][2], s[j1][3]);
                {
                    __nv_bfloat162 t0 = *(__nv_bfloat162*)&ph[0];
                    __nv_bfloat162 t1 = *(__nv_bfloat162*)&ph[1];
                    __nv_bfloat162 t2 = *(__nv_bfloat162*)&ph[2];
                    __nv_bfloat162 t3 = *(__nv_bfloat162*)&ph[3];
                    pl[0] = pack_bf16x2(s[j0][0] - __bfloat162float(t0.x),
                                        s[j0][1] - __bfloat162float(t0.y));
                    pl[1] = pack_bf16x2(s[j0][2] - __bfloat162float(t1.x),
                                        s[j0][3] - __bfloat162float(t1.y));
                    pl[2] = pack_bf16x2(s[j1][0] - __bfloat162float(t2.x),
                                        s[j1][1] - __bfloat162float(t2.y));
                    pl[3] = pack_bf16x2(s[j1][2] - __bfloat162float(t3.x),
                                        s[j1][3] - __bfloat162float(t3.y));
                }
                #pragma unroll
                for (int np = 0; np < 6; np++) {
                    uint32_t voff = (uint32_t)((ks*16 + vrow) * ALDS + np*16 + vn8) * 2;
                    uint32_t vh_[4], vl_[4];
                    ldsm4t(vh_[0], vh_[1], vh_[2], vh_[3], sVh + voff);
                    ldsm4t(vl_[0], vl_[1], vl_[2], vl_[3], sVl + voff);
                    mma16816(o[2*np],   ph[0],ph[1],ph[2],ph[3], vh_[0], vh_[1]);
                    mma16816(o[2*np],   ph[0],ph[1],ph[2],ph[3], vl_[0], vl_[1]);
                    mma16816(o[2*np],   pl[0],pl[1],pl[2],pl[3], vh_[0], vh_[1]);
                    mma16816(o[2*np+1], ph[0],ph[1],ph[2],ph[3], vh_[2], vh_[3]);
                    mma16816(o[2*np+1], ph[0],ph[1],ph[2],ph[3], vl_[2], vl_[3]);
                    mma16816(o[2*np+1], pl[0],pl[1],pl[2],pl[3], vh_[2], vh_[3]);
                }
            }
        }
        if (++bb == ASTAGES) bb = 0;
    }

    const float il0 = 1.f / l0, il1 = 1.f / l1;
    const size_t mrow0 = (size_t)(b * S_ + row_g0) * H_;
    const size_t mrow1 = mrow0 + 8 * (size_t)H_;
    #pragma unroll
    for (int t = 0; t < 12; t++) {
        int col = h * HD + t*8 + c2_;
        float v0 = o[t][0] * il0, v1 = o[t][1] * il0;
        float v2 = o[t][2] * il1, v3 = o[t][3] * il1;
        uint32_t h0 = pack_bf16x2(v0, v1);
        uint32_t h1 = pack_bf16x2(v2, v3);
        __nv_bfloat162 hh0 = *(__nv_bfloat162*)&h0;
        __nv_bfloat162 hh1 = *(__nv_bfloat162*)&h1;
        uint32_t l0p = pack_bf16x2(v0 - __bfloat162float(hh0.x),
                                   v1 - __bfloat162float(hh0.y));
        uint32_t l1p = pack_bf16x2(v2 - __bfloat162float(hh1.x),
                                   v3 - __bfloat162float(hh1.y));
        *(uint32_t*)(ahi + mrow0 + col) = h0;
        *(uint32_t*)(alo + mrow0 + col) = l0p;
        *(uint32_t*)(ahi + mrow1 + col) = h1;
        *(uint32_t*)(alo + mrow1 + col) = l1p;
    }
}

// ---------------------------------------------------------------------------

extern "C" void kernel_launch(void* const* d_in, const int* in_sizes, int n_in,
                              void* d_out, int out_size)
{
    const float* hidden = (const float*)d_in[0];
    const float* w_qkv  = (const float*)d_in[2];
    const float* w_o    = (const float*)d_in[3];
    float* out = (float*)d_out;

    float *qkv;
    __nv_bfloat16 *h_hi, *h_lo, *wq_hi, *wq_lo, *wo_hi, *wo_lo, *a_hi, *a_lo;
    __nv_bfloat16 *q_hi, *q_lo, *k_hi, *k_lo, *v_hi, *v_lo;
    cudaGetSymbolAddress((void**)&qkv,   g_qkv);
    cudaGetSymbolAddress((void**)&h_hi,  g_h_hi);
    cudaGetSymbolAddress((void**)&h_lo,  g_h_lo);
    cudaGetSymbolAddress((void**)&wq_hi, g_wq_hi);
    cudaGetSymbolAddress((void**)&wq_lo, g_wq_lo);
    cudaGetSymbolAddress((void**)&wo_hi, g_wo_hi);
    cudaGetSymbolAddress((void**)&wo_lo, g_wo_lo);
    cudaGetSymbolAddress((void**)&a_hi,  g_a_hi);
    cudaGetSymbolAddress((void**)&a_lo,  g_a_lo);
    cudaGetSymbolAddress((void**)&q_hi,  g_q_hi);
    cudaGetSymbolAddress((void**)&q_lo,  g_q_lo);
    cudaGetSymbolAddress((void**)&k_hi,  g_k_hi);
    cudaGetSymbolAddress((void**)&k_lo,  g_k_lo);
    cudaGetSymbolAddress((void**)&v_hi,  g_v_hi);
    cudaGetSymbolAddress((void**)&v_lo,  g_v_lo);

    cudaFuncSetAttribute(gemm_3xbf16, cudaFuncAttributeMaxDynamicSharedMemorySize, GEMM_SMEM);
    cudaFuncSetAttribute(attn_mma,    cudaFuncAttributeMaxDynamicSharedMemorySize, ATT_SMEM);

    {
        int n4;
        n4 = (M_ * H_) / 4;
        split_f32<<<(n4 + 255)/256, 256>>>(hidden, h_hi, h_lo, n4);
        n4 = (QKV_W * H_) / 4;
        split_f32<<<(n4 + 255)/256, 256>>>(w_qkv, wq_hi, wq_lo, n4);
        n4 = (H_ * H_) / 4;
        split_f32<<<(n4 + 255)/256, 256>>>(w_o, wo_hi, wo_lo, n4);
    }

    gemm_3xbf16<<<dim3(QKV_W/128, M_/128), 256, GEMM_SMEM>>>(
        h_hi, h_lo, wq_hi, wq_lo, qkv, QKV_W, H_);

    {
        int total = B_ * S_ * (NH + NKV) * (HD/2);
        rope_split<<<(total + 255)/256, 256>>>(qkv, q_hi, q_lo, k_hi, k_lo);
        int vt = B_ * S_ * NKV * (HD/4);
        v_split<<<(vt + 255)/256, 256>>>(qkv, v_hi, v_lo);
    }

    attn_mma<<<dim3(S_/BLKQ, B_*NH), 128, ATT_SMEM>>>(
        q_hi, q_lo, k_hi, k_lo, v_hi, v_lo, a_hi, a_lo);

    gemm_3xbf16<<<dim3(H_/128, M_/128), 256, GEMM_SMEM>>>(
        a_hi, a_lo, wo_hi, wo_lo, out, H_, H_);
}

// round 8
// speedup vs baseline: 1.3487x; 1.3487x over previous
#include <cuda_runtime.h>
#include <cuda_bf16.h>
#include <cuda_fp16.h>
#include <math.h>
#include <stdint.h>

#define B_   2
#define S_   2048
#define H_   3072
#define NH   32
#define NKV  8
#define HD   96
#define QKV_W (NH*HD + 2*NKV*HD)   // 4608
#define M_   (B_*S_)               // 4096

// ---------------- scratch (device globals: allocation-free rule) -----------
__device__ float g_qkv[(size_t)M_ * QKV_W];
__device__ __half g_h_f16[(size_t)M_ * H_];
__device__ __half g_wq_hi[(size_t)QKV_W * H_], g_wq_lo[(size_t)QKV_W * H_];
__device__ __half g_wo_hi[(size_t)H_ * H_],    g_wo_lo[(size_t)H_ * H_];
__device__ __half g_a_f16[(size_t)M_ * H_];
__device__ __nv_bfloat16 g_q_hi[(size_t)B_*NH*S_*HD],  g_q_lo[(size_t)B_*NH*S_*HD];
__device__ __nv_bfloat16 g_k_hi[(size_t)B_*NKV*S_*HD], g_k_lo[(size_t)B_*NKV*S_*HD];
__device__ __nv_bfloat16 g_v_hi[(size_t)B_*NKV*S_*HD], g_v_lo[(size_t)B_*NKV*S_*HD];

// ---------------- base-target PTX helpers ----------------------------------
__device__ __forceinline__ void cp_async16(uint32_t dst, const void* src) {
    asm volatile("cp.async.cg.shared.global [%0], [%1], 16;"
                 :: "r"(dst), "l"(src) : "memory");
}
#define CP_COMMIT() asm volatile("cp.async.commit_group;" ::: "memory")
#define CP_WAIT(n)  asm volatile("cp.async.wait_group %0;" :: "n"(n) : "memory")

__device__ __forceinline__ void ldsm4(uint32_t& r0, uint32_t& r1, uint32_t& r2,
                                      uint32_t& r3, uint32_t addr) {
    asm volatile("ldmatrix.sync.aligned.m8n8.x4.shared.b16 {%0,%1,%2,%3}, [%4];"
                 : "=r"(r0), "=r"(r1), "=r"(r2), "=r"(r3) : "r"(addr));
}
__device__ __forceinline__ void ldsm4t(uint32_t& r0, uint32_t& r1, uint32_t& r2,
                                       uint32_t& r3, uint32_t addr) {
    asm volatile("ldmatrix.sync.aligned.m8n8.x4.trans.shared.b16 {%0,%1,%2,%3}, [%4];"
                 : "=r"(r0), "=r"(r1), "=r"(r2), "=r"(r3) : "r"(addr));
}
// bf16 mma (attention)
__device__ __forceinline__ void mma16816(float* c, uint32_t a0, uint32_t a1,
                                         uint32_t a2, uint32_t a3,
                                         uint32_t b0, uint32_t b1) {
    asm volatile(
        "mma.sync.aligned.m16n8k16.row.col.f32.bf16.bf16.f32 "
        "{%0,%1,%2,%3}, {%4,%5,%6,%7}, {%8,%9}, {%0,%1,%2,%3};"
        : "+f"(c[0]), "+f"(c[1]), "+f"(c[2]), "+f"(c[3])
        : "r"(a0), "r"(a1), "r"(a2), "r"(a3), "r"(b0), "r"(b1));
}
// fp16 mma (GEMMs)
__device__ __forceinline__ void mma16816h(float* c, uint32_t a0, uint32_t a1,
                                          uint32_t a2, uint32_t a3,
                                          uint32_t b0, uint32_t b1) {
    asm volatile(
        "mma.sync.aligned.m16n8k16.row.col.f32.f16.f16.f32 "
        "{%0,%1,%2,%3}, {%4,%5,%6,%7}, {%8,%9}, {%0,%1,%2,%3};"
        : "+f"(c[0]), "+f"(c[1]), "+f"(c[2]), "+f"(c[3])
        : "r"(a0), "r"(a1), "r"(a2), "r"(a3), "r"(b0), "r"(b1));
}

__device__ __forceinline__ uint32_t pack_bf16x2(float lo, float hi) {
    __nv_bfloat162 p = __floats2bfloat162_rn(lo, hi);
    return *(uint32_t*)&p;
}
__device__ __forceinline__ uint32_t pack_f16x2(float lo, float hi) {
    __half2 p = __floats2half2_rn(lo, hi);
    return *(uint32_t*)&p;
}

// ---------------------------------------------------------------------------
// fp32 -> fp16 round (activations) and fp32 -> fp16 hi/lo split (weights)
// ---------------------------------------------------------------------------
__global__ void round_f16(const float* __restrict__ x, __half* __restrict__ h, int n4)
{
    int i = blockIdx.x * blockDim.x + threadIdx.x;
    if (i >= n4) return;
    float4 v = ((const float4*)x)[i];
    ((__half2*)h)[2*i]   = __floats2half2_rn(v.x, v.y);
    ((__half2*)h)[2*i+1] = __floats2half2_rn(v.z, v.w);
}

__global__ void split_f16(const float* __restrict__ x,
                          __half* __restrict__ hi, __half* __restrict__ lo, int n4)
{
    int i = blockIdx.x * blockDim.x + threadIdx.x;
    if (i >= n4) return;
    float4 v = ((const float4*)x)[i];
    float h0 = __half2float(__float2half_rn(v.x));
    float h1 = __half2float(__float2half_rn(v.y));
    float h2 = __half2float(__float2half_rn(v.z));
    float h3 = __half2float(__float2half_rn(v.w));
    ((__half2*)hi)[2*i]   = __floats2half2_rn(h0, h1);
    ((__half2*)hi)[2*i+1] = __floats2half2_rn(h2, h3);
    ((__half2*)lo)[2*i]   = __floats2half2_rn(v.x - h0, v.y - h1);
    ((__half2*)lo)[2*i+1] = __floats2half2_rn(v.z - h2, v.w - h3);
}

// ---------------------------------------------------------------------------
// 2-pass fp16 mma.sync GEMM (NT): C = A * B^T, A fp16 (rounded),
// B split fp16 hi/lo. 128x128 CTA tile, BK=32, 2-stage, 2 CTAs/SM.
// ---------------------------------------------------------------------------
#define BK      32
#define LDS_    40
#define PLANE_B (128 * LDS_ * 2)      // 10240
#define BUF_B   (3 * PLANE_B)         // 30720  (A | Bh | Bl)
#define GEMM_SMEM (2 * BUF_B)         // 61440

__global__ __launch_bounds__(256, 2) void gemm_2xf16(
    const __half* __restrict__ A,
    const __half* __restrict__ Bhi, const __half* __restrict__ Blo,
    float* __restrict__ C, int N, int K)
{
    extern __shared__ __align__(128) char smc[];
    const uint32_t sbase = (uint32_t)__cvta_generic_to_shared(smc);
    const int tid  = threadIdx.x;
    const int warp = tid >> 5, lane = tid & 31;
    const int bm = blockIdx.y * 128, bn = blockIdx.x * 128;
    const int wm = (warp >> 2) * 64;
    const int wn = (warp & 3) * 32;

    const __half* srcs[3] = {
        A + (size_t)bm * K, Bhi + (size_t)bn * K, Blo + (size_t)bn * K };

    const int nch = K / BK;

    auto load_chunk = [&](int kc, int bb) {
        uint32_t sb = sbase + bb * BUF_B;
        #pragma unroll
        for (int p = 0; p < 3; p++) {
            const __half* sp = srcs[p] + kc * BK;
            uint32_t pb = sb + p * PLANE_B;
            #pragma unroll
            for (int t = 0; t < 2; t++) {
                int f = tid + t * 256;
                int r = f >> 2, j = f & 3;
                cp_async16(pb + r * (LDS_ * 2) + j * 16,
                           sp + (size_t)r * K + j * 8);
            }
        }
        CP_COMMIT();
    };

    float c[4][4][4];
    #pragma unroll
    for (int i = 0; i < 4; i++)
        #pragma unroll
        for (int j = 0; j < 4; j++)
            #pragma unroll
            for (int q = 0; q < 4; q++) c[i][j][q] = 0.f;

    load_chunk(0, 0);

    const int arow = lane & 15;
    const int ak8  = (lane >> 4) * 8;
    const int brow = (lane & 7) + ((lane >> 4) << 3);
    const int bk8  = ((lane >> 3) & 1) * 8;

    #pragma unroll 1
    for (int kc = 0; kc < nch; kc++) {
        const int bb = kc & 1;
        CP_WAIT(0);
        __syncthreads();
        if (kc + 1 < nch) load_chunk(kc + 1, bb ^ 1);

        const uint32_t sA  = sbase + bb * BUF_B;
        const uint32_t sBh = sA + PLANE_B;
        const uint32_t sBl = sA + 2 * PLANE_B;

        #pragma unroll
        for (int ks = 0; ks < 2; ks++) {
            const int k0 = ks * 16;
            uint32_t bh[4][2], bl[4][2];
            #pragma unroll
            for (int tp = 0; tp < 2; tp++) {
                uint32_t off = (uint32_t)((wn + tp*16 + brow) * LDS_ + k0 + bk8) * 2;
                ldsm4(bh[tp*2][0], bh[tp*2][1], bh[tp*2+1][0], bh[tp*2+1][1], sBh + off);
                ldsm4(bl[tp*2][0], bl[tp*2][1], bl[tp*2+1][0], bl[tp*2+1][1], sBl + off);
            }
            #pragma unroll
            for (int ti = 0; ti < 4; ti++) {
                uint32_t off = (uint32_t)((wm + ti*16 + arow) * LDS_ + k0 + ak8) * 2;
                uint32_t ah[4];
                ldsm4(ah[0], ah[1], ah[2], ah[3], sA + off);
                #pragma unroll
                for (int tj = 0; tj < 4; tj++) {
                    mma16816h(c[ti][tj], ah[0], ah[1], ah[2], ah[3],
                              bh[tj][0], bh[tj][1]);
                    mma16816h(c[ti][tj], ah[0], ah[1], ah[2], ah[3],
                              bl[tj][0], bl[tj][1]);
                }
            }
        }
    }

    const int cr = lane >> 2, cc = (lane & 3) * 2;
    #pragma unroll
    for (int ti = 0; ti < 4; ti++) {
        #pragma unroll
        for (int tj = 0; tj < 4; tj++) {
            int r0 = bm + wm + ti*16 + cr;
            int col = bn + wn + tj*8 + cc;
            *(float2*)(C + (size_t)r0 * N + col)       = make_float2(c[ti][tj][0], c[ti][tj][1]);
            *(float2*)(C + (size_t)(r0 + 8) * N + col) = make_float2(c[ti][tj][2], c[ti][tj][3]);
        }
    }
}

// ---------------------------------------------------------------------------
// RoPE + hi/lo split into head-major bf16 planes (attention operands).
// ---------------------------------------------------------------------------
__global__ void rope_split(const float* __restrict__ qkv,
                           __nv_bfloat16* __restrict__ qhi, __nv_bfloat16* __restrict__ qlo,
                           __nv_bfloat16* __restrict__ khi, __nv_bfloat16* __restrict__ klo)
{
    const int total = B_ * S_ * (NH + NKV) * (HD / 2);
    int i = blockIdx.x * blockDim.x + threadIdx.x;
    if (i >= total) return;
    int d    = i % (HD/2);
    int t    = i / (HD/2);
    int head = t % (NH + NKV);
    int bs   = t / (NH + NKV);
    int b    = bs / S_;
    int s    = bs % S_;

    float inv = expf(-(float)d * (logf(10000.0f) / 48.0f));
    float ang = (float)s * inv;
    float sn, cs;
    sincosf(ang, &sn, &cs);

    const float* base = qkv + (size_t)bs * QKV_W + head * HD;
    float x1 = base[d];
    float x2 = base[d + 48];
    float y1 = x1 * cs - x2 * sn;
    float y2 = x2 * cs + x1 * sn;

    __nv_bfloat16 *hi, *lo;
    size_t idx;
    if (head < NH) {
        const float scale = 0.10206207261596577f;
        y1 *= scale; y2 *= scale;
        idx = ((size_t)(b * NH + head) * S_ + s) * HD;
        hi = qhi; lo = qlo;
    } else {
        idx = ((size_t)(b * NKV + (head - NH)) * S_ + s) * HD;
        hi = khi; lo = klo;
    }
    __nv_bfloat16 h1 = __float2bfloat16_rn(y1);
    __nv_bfloat16 h2 = __float2bfloat16_rn(y2);
    hi[idx + d]      = h1;
    hi[idx + d + 48] = h2;
    lo[idx + d]      = __float2bfloat16_rn(y1 - __bfloat162float(h1));
    lo[idx + d + 48] = __float2bfloat16_rn(y2 - __bfloat162float(h2));
}

__global__ void v_split(const float* __restrict__ qkv,
                        __nv_bfloat16* __restrict__ vhi, __nv_bfloat16* __restrict__ vlo)
{
    const int total = B_ * S_ * NKV * (HD / 4);
    int i = blockIdx.x * blockDim.x + threadIdx.x;
    if (i >= total) return;
    int d4  = i % (HD/4);
    int t   = i / (HD/4);
    int kvh = t % NKV;
    int bs  = t / NKV;
    int b   = bs / S_;
    int s   = bs % S_;

    const float* src = qkv + (size_t)bs * QKV_W + NH*HD + NKV*HD + kvh*HD + d4*4;
    float4 v = *(const float4*)src;
    size_t idx = ((size_t)(b * NKV + kvh) * S_ + s) * HD + d4*4;
    __nv_bfloat16 h0 = __float2bfloat16_rn(v.x);
    __nv_bfloat16 h1 = __float2bfloat16_rn(v.y);
    __nv_bfloat16 h2 = __float2bfloat16_rn(v.z);
    __nv_bfloat16 h3 = __float2bfloat16_rn(v.w);
    *(__nv_bfloat162*)(vhi + idx)     = __nv_bfloat162(h0, h1);
    *(__nv_bfloat162*)(vhi + idx + 2) = __nv_bfloat162(h2, h3);
    *(__nv_bfloat162*)(vlo + idx) =
        __nv_bfloat162(__float2bfloat16_rn(v.x - __bfloat162float(h0)),
                       __float2bfloat16_rn(v.y - __bfloat162float(h1)));
    *(__nv_bfloat162*)(vlo + idx + 2) =
        __nv_bfloat162(__float2bfloat16_rn(v.z - __bfloat162float(h2)),
                       __float2bfloat16_rn(v.w - __bfloat162float(h3)));
}

// ---------------------------------------------------------------------------
// Flash attention on mma.sync (3xBF16) — round-6 WIN config:
// CTA: 128 queries, 8 warps x 16 rows, 64-key tiles, 3-stage KV ring.
// Epilogue writes single fp16 plane (feeds 2-pass fp16 output GEMM).
// ---------------------------------------------------------------------------
#define ALDS   104
#define QBYTES (128 * ALDS * 2)         // 26624
#define KVTILE (64 * ALDS * 2)          // 13312
#define KVBUF  (4 * KVTILE)             // 53248
#define ASTAGES 3
#define ATT_SMEM (2*QBYTES + ASTAGES*KVBUF)   // 212992

__global__ __launch_bounds__(256, 1) void attn_mma(
    const __nv_bfloat16* __restrict__ qhi, const __nv_bfloat16* __restrict__ qlo,
    const __nv_bfloat16* __restrict__ khi, const __nv_bfloat16* __restrict__ klo,
    const __nv_bfloat16* __restrict__ vhi, const __nv_bfloat16* __restrict__ vlo,
    __half* __restrict__ aout)
{
    extern __shared__ __align__(128) char smc[];
    const uint32_t sb  = (uint32_t)__cvta_generic_to_shared(smc);
    const uint32_t sQh = sb, sQl = sb + QBYTES;
    const uint32_t sKV = sb + 2 * QBYTES;

    const int tid  = threadIdx.x;
    const int warp = tid >> 5, lane = tid & 31;
    const int qt = blockIdx.x;
    const int bh = blockIdx.y;
    const int b  = bh >> 5, h = bh & 31, kvh = h >> 2;
    const int q0 = qt * 128;
    const int wm = warp * 16;

    const __nv_bfloat16* qsh = qhi + ((size_t)(b*NH + h) * S_ + q0) * HD;
    const __nv_bfloat16* qsl = qlo + ((size_t)(b*NH + h) * S_ + q0) * HD;
    const __nv_bfloat16* ksh = khi + (size_t)(b*NKV + kvh) * S_ * HD;
    const __nv_bfloat16* ksl = klo + (size_t)(b*NKV + kvh) * S_ * HD;
    const __nv_bfloat16* vsh = vhi + (size_t)(b*NKV + kvh) * S_ * HD;
    const __nv_bfloat16* vsl = vlo + (size_t)(b*NKV + kvh) * S_ * HD;

    #pragma unroll
    for (int u = 0; u < 6; u++) {
        int f = tid + u * 256;
        int r = f / 12, cidx = f % 12;
        cp_async16(sQh + r * (ALDS*2) + cidx * 16, qsh + (size_t)r * HD + cidx * 8);
        cp_async16(sQl + r * (ALDS*2) + cidx * 16, qsl + (size_t)r * HD + cidx * 8);
    }

    auto load_kv = [&](int kt, int bb) {
        uint32_t base = sKV + bb * KVBUF;
        int k0 = kt * 64;
        #pragma unroll
        for (int u = 0; u < 3; u++) {
            int f = tid + u * 256;
            int r = f / 12, cidx = f % 12;
            size_t g = (size_t)(k0 + r) * HD + cidx * 8;
            uint32_t o = r * (ALDS*2) + cidx * 16;
            cp_async16(base + 0*KVTILE + o, ksh + g);
            cp_async16(base + 1*KVTILE + o, ksl + g);
            cp_async16(base + 2*KVTILE + o, vsh + g);
            cp_async16(base + 3*KVTILE + o, vsl + g);
        }
        CP_COMMIT();
    };

    const int nkt = 2 * qt + 2;
    load_kv(0, 0);
    if (nkt > 1) load_kv(1, 1); else CP_COMMIT();

    const int arow = lane & 15;
    const int ak8  = (lane >> 4) * 8;
    const int brow = (lane & 7) + ((lane >> 4) << 3);
    const int bk8  = ((lane >> 3) & 1) * 8;
    const int vrow = lane & 15;
    const int vn8  = (lane >> 4) * 8;
    const int r_   = lane >> 2;
    const int c2_  = (lane & 3) * 2;

    float o[12][4];
    #pragma unroll
    for (int t = 0; t < 12; t++)
        #pragma unroll
        for (int q = 0; q < 4; q++) o[t][q] = 0.f;
    float m0 = -1e30f, m1 = -1e30f, l0 = 0.f, l1 = 0.f;

    const int row_g0 = q0 + wm + r_;
    const int wmax   = q0 + wm + 15;

    int bb = 0;
    #pragma unroll 1
    for (int kt = 0; kt < nkt; kt++) {
        const int k0 = kt * 64;
        CP_WAIT(1);
        __syncthreads();
        if (kt + 2 < nkt) {
            int nb = bb + 2; if (nb >= ASTAGES) nb -= ASTAGES;
            load_kv(kt + 2, nb);
        } else CP_COMMIT();

        if (k0 <= wmax) {
            const uint32_t sKh = sKV + bb * KVBUF;
            const uint32_t sKl = sKh + KVTILE;
            const uint32_t sVh = sKh + 2 * KVTILE;
            const uint32_t sVl = sKh + 3 * KVTILE;

            float s[8][4];
            #pragma unroll
            for (int t = 0; t < 8; t++)
                #pragma unroll
                for (int q = 0; q < 4; q++) s[t][q] = 0.f;

            #pragma unroll
            for (int ks = 0; ks < 6; ks++) {
                uint32_t aoff = (uint32_t)((wm + arow) * ALDS + ks*16 + ak8) * 2;
                uint32_t ah[4], al[4];
                ldsm4(ah[0], ah[1], ah[2], ah[3], sQh + aoff);
                ldsm4(al[0], al[1], al[2], al[3], sQl + aoff);
                #pragma unroll
                for (int np = 0; np < 4; np++) {
                    uint32_t boff = (uint32_t)((np*16 + brow) * ALDS + ks*16 + bk8) * 2;
                    uint32_t bh_[4], bl_[4];
                    ldsm4(bh_[0], bh_[1], bh_[2], bh_[3], sKh + boff);
                    ldsm4(bl_[0], bl_[1], bl_[2], bl_[3], sKl + boff);
                    mma16816(s[2*np],   ah[0],ah[1],ah[2],ah[3], bh_[0], bh_[1]);
                    mma16816(s[2*np],   ah[0],ah[1],ah[2],ah[3], bl_[0], bl_[1]);
                    mma16816(s[2*np],   al[0],al[1],al[2],al[3], bh_[0], bh_[1]);
                    mma16816(s[2*np+1], ah[0],ah[1],ah[2],ah[3], bh_[2], bh_[3]);
                    mma16816(s[2*np+1], ah[0],ah[1],ah[2],ah[3], bl_[2], bl_[3]);
                    mma16816(s[2*np+1], al[0],al[1],al[2],al[3], bh_[2], bh_[3]);
                }
            }

            if (k0 + 63 > q0 + wm) {
                #pragma unroll
                for (int t = 0; t < 8; t++) {
                    int col = k0 + t*8 + c2_;
                    if (col     > row_g0)     s[t][0] = -1e30f;
                    if (col + 1 > row_g0)     s[t][1] = -1e30f;
                    if (col     > row_g0 + 8) s[t][2] = -1e30f;
                    if (col + 1 > row_g0 + 8) s[t][3] = -1e30f;
                }
            }

            float mx0 = -1e30f, mx1 = -1e30f;
            #pragma unroll
            for (int t = 0; t < 8; t++) {
                mx0 = fmaxf(mx0, fmaxf(s[t][0], s[t][1]));
                mx1 = fmaxf(mx1, fmaxf(s[t][2], s[t][3]));
            }
            mx0 = fmaxf(mx0, __shfl_xor_sync(0xffffffff, mx0, 1));
            mx0 = fmaxf(mx0, __shfl_xor_sync(0xffffffff, mx0, 2));
            mx1 = fmaxf(mx1, __shfl_xor_sync(0xffffffff, mx1, 1));
            mx1 = fmaxf(mx1, __shfl_xor_sync(0xffffffff, mx1, 2));

            float mn0 = fmaxf(m0, mx0), mn1 = fmaxf(m1, mx1);
            float al0 = __expf(m0 - mn0), al1 = __expf(m1 - mn1);
            m0 = mn0; m1 = mn1;

            float sum0 = 0.f, sum1 = 0.f;
            #pragma unroll
            for (int t = 0; t < 8; t++) {
                s[t][0] = __expf(s[t][0] - m0);
                s[t][1] = __expf(s[t][1] - m0);
                s[t][2] = __expf(s[t][2] - m1);
                s[t][3] = __expf(s[t][3] - m1);
                sum0 += s[t][0] + s[t][1];
                sum1 += s[t][2] + s[t][3];
            }
            sum0 += __shfl_xor_sync(0xffffffff, sum0, 1);
            sum0 += __shfl_xor_sync(0xffffffff, sum0, 2);
            sum1 += __shfl_xor_sync(0xffffffff, sum1, 1);
            sum1 += __shfl_xor_sync(0xffffffff, sum1, 2);
            l0 = l0 * al0 + sum0;
            l1 = l1 * al1 + sum1;

            #pragma unroll
            for (int t = 0; t < 12; t++) {
                o[t][0] *= al0; o[t][1] *= al0;
                o[t][2] *= al1; o[t][3] *= al1;
            }

            #pragma unroll
            for (int ks = 0; ks < 4; ks++) {
                const int j0 = 2*ks, j1 = 2*ks + 1;
                uint32_t ph[4], pl[4];
                ph[0] = pack_bf16x2(s[j0][0], s[j0][1]);
                ph[1] = pack_bf16x2(s[j0][2], s[j0][3]);
                ph[2] = pack_bf16x2(s[j1][0], s[j1][1]);
                ph[3] = pack_bf16x2(s[j1][2], s[j1][3]);
                {
                    __nv_bfloat162 t0 = *(__nv_bfloat162*)&ph[0];
                    __nv_bfloat162 t1 = *(__nv_bfloat162*)&ph[1];
                    __nv_bfloat162 t2 = *(__nv_bfloat162*)&ph[2];
                    __nv_bfloat162 t3 = *(__nv_bfloat162*)&ph[3];
                    pl[0] = pack_bf16x2(s[j0][0] - __bfloat162float(t0.x),
                                        s[j0][1] - __bfloat162float(t0.y));
                    pl[1] = pack_bf16x2(s[j0][2] - __bfloat162float(t1.x),
                                        s[j0][3] - __bfloat162float(t1.y));
                    pl[2] = pack_bf16x2(s[j1][0] - __bfloat162float(t2.x),
                                        s[j1][1] - __bfloat162float(t2.y));
                    pl[3] = pack_bf16x2(s[j1][2] - __bfloat162float(t3.x),
                                        s[j1][3] - __bfloat162float(t3.y));
                }
                #pragma unroll
                for (int np = 0; np < 6; np++) {
                    uint32_t voff = (uint32_t)((ks*16 + vrow) * ALDS + np*16 + vn8) * 2;
                    uint32_t vh_[4], vl_[4];
                    ldsm4t(vh_[0], vh_[1], vh_[2], vh_[3], sVh + voff);
                    ldsm4t(vl_[0], vl_[1], vl_[2], vl_[3], sVl + voff);
                    mma16816(o[2*np],   ph[0],ph[1],ph[2],ph[3], vh_[0], vh_[1]);
                    mma16816(o[2*np],   ph[0],ph[1],ph[2],ph[3], vl_[0], vl_[1]);
                    mma16816(o[2*np],   pl[0],pl[1],pl[2],pl[3], vh_[0], vh_[1]);
                    mma16816(o[2*np+1], ph[0],ph[1],ph[2],ph[3], vh_[2], vh_[3]);
                    mma16816(o[2*np+1], ph[0],ph[1],ph[2],ph[3], vl_[2], vl_[3]);
                    mma16816(o[2*np+1], pl[0],pl[1],pl[2],pl[3], vh_[2], vh_[3]);
                }
            }
        }
        if (++bb == ASTAGES) bb = 0;
    }

    // epilogue: normalize, round to fp16 plane (feeds 2-pass fp16 GEMM)
    const float il0 = 1.f / l0, il1 = 1.f / l1;
    const size_t mrow0 = (size_t)(b * S_ + row_g0) * H_;
    const size_t mrow1 = mrow0 + 8 * (size_t)H_;
    #pragma unroll
    for (int t = 0; t < 12; t++) {
        int col = h * HD + t*8 + c2_;
        *(uint32_t*)(aout + mrow0 + col) = pack_f16x2(o[t][0]*il0, o[t][1]*il0);
        *(uint32_t*)(aout + mrow1 + col) = pack_f16x2(o[t][2]*il1, o[t][3]*il1);
    }
}

// ---------------------------------------------------------------------------

extern "C" void kernel_launch(void* const* d_in, const int* in_sizes, int n_in,
                              void* d_out, int out_size)
{
    const float* hidden = (const float*)d_in[0];
    const float* w_qkv  = (const float*)d_in[2];
    const float* w_o    = (const float*)d_in[3];
    float* out = (float*)d_out;

    float *qkv;
    __half *h_f16, *wq_hi, *wq_lo, *wo_hi, *wo_lo, *a_f16;
    __nv_bfloat16 *q_hi, *q_lo, *k_hi, *k_lo, *v_hi, *v_lo;
    cudaGetSymbolAddress((void**)&qkv,   g_qkv);
    cudaGetSymbolAddress((void**)&h_f16, g_h_f16);
    cudaGetSymbolAddress((void**)&wq_hi, g_wq_hi);
    cudaGetSymbolAddress((void**)&wq_lo, g_wq_lo);
    cudaGetSymbolAddress((void**)&wo_hi, g_wo_hi);
    cudaGetSymbolAddress((void**)&wo_lo, g_wo_lo);
    cudaGetSymbolAddress((void**)&a_f16, g_a_f16);
    cudaGetSymbolAddress((void**)&q_hi,  g_q_hi);
    cudaGetSymbolAddress((void**)&q_lo,  g_q_lo);
    cudaGetSymbolAddress((void**)&k_hi,  g_k_hi);
    cudaGetSymbolAddress((void**)&k_lo,  g_k_lo);
    cudaGetSymbolAddress((void**)&v_hi,  g_v_hi);
    cudaGetSymbolAddress((void**)&v_lo,  g_v_lo);

    cudaFuncSetAttribute(gemm_2xf16, cudaFuncAttributeMaxDynamicSharedMemorySize, GEMM_SMEM);
    cudaFuncSetAttribute(attn_mma,   cudaFuncAttributeMaxDynamicSharedMemorySize, ATT_SMEM);

    // 1) activations rounded to fp16; weights split fp16 hi/lo
    {
        int n4;
        n4 = (M_ * H_) / 4;
        round_f16<<<(n4 + 255)/256, 256>>>(hidden, h_f16, n4);
        n4 = (QKV_W * H_) / 4;
        split_f16<<<(n4 + 255)/256, 256>>>(w_qkv, wq_hi, wq_lo, n4);
        n4 = (H_ * H_) / 4;
        split_f16<<<(n4 + 255)/256, 256>>>(w_o, wo_hi, wo_lo, n4);
    }

    // 2) QKV projection (2-pass fp16 HMMA)
    gemm_2xf16<<<dim3(QKV_W/128, M_/128), 256, GEMM_SMEM>>>(
        h_f16, wq_hi, wq_lo, qkv, QKV_W, H_);

    // 3) RoPE + split to head-major bf16 planes; V split
    {
        int total = B_ * S_ * (NH + NKV) * (HD/2);
        rope_split<<<(total + 255)/256, 256>>>(qkv, q_hi, q_lo, k_hi, k_lo);
        int vt = B_ * S_ * NKV * (HD/4);
        v_split<<<(vt + 255)/256, 256>>>(qkv, v_hi, v_lo);
    }

    // 4) causal GQA flash attention (3xBF16), writes fp16 plane
    attn_mma<<<dim3(S_/128, B_*NH), 256, ATT_SMEM>>>(
        q_hi, q_lo, k_hi, k_lo, v_hi, v_lo, a_f16);

    // 5) output projection (2-pass fp16 HMMA)
    gemm_2xf16<<<dim3(H_/128, M_/128), 256, GEMM_SMEM>>>(
        a_f16, wo_hi, wo_lo, out, H_, H_);
}

// round 9
// speedup vs baseline: 1.5324x; 1.1361x over previous
#include <cuda_runtime.h>
#include <cuda_bf16.h>
#include <cuda_fp16.h>
#include <math.h>
#include <stdint.h>

#define B_   2
#define S_   2048
#define H_   3072
#define NH   32
#define NKV  8
#define HD   96
#define QKV_W (NH*HD + 2*NKV*HD)   // 4608
#define M_   (B_*S_)               // 4096

// ---------------- scratch (device globals: allocation-free rule) -----------
__device__ float g_qkv[(size_t)M_ * QKV_W];
__device__ __half g_h_f16[(size_t)M_ * H_];
__device__ __half g_wq_hi[(size_t)QKV_W * H_], g_wq_lo[(size_t)QKV_W * H_];
__device__ __half g_wo_hi[(size_t)H_ * H_],    g_wo_lo[(size_t)H_ * H_];
__device__ __half g_a_f16[(size_t)M_ * H_];
__device__ __half g_q_hi[(size_t)B_*NH*S_*HD],  g_q_lo[(size_t)B_*NH*S_*HD];
__device__ __half g_k_f16[(size_t)B_*NKV*S_*HD];
__device__ __half g_v_hi[(size_t)B_*NKV*S_*HD], g_v_lo[(size_t)B_*NKV*S_*HD];

// ---------------- base-target PTX helpers ----------------------------------
__device__ __forceinline__ void cp_async16(uint32_t dst, const void* src) {
    asm volatile("cp.async.cg.shared.global [%0], [%1], 16;"
                 :: "r"(dst), "l"(src) : "memory");
}
#define CP_COMMIT() asm volatile("cp.async.commit_group;" ::: "memory")
#define CP_WAIT(n)  asm volatile("cp.async.wait_group %0;" :: "n"(n) : "memory")

__device__ __forceinline__ void ldsm4(uint32_t& r0, uint32_t& r1, uint32_t& r2,
                                      uint32_t& r3, uint32_t addr) {
    asm volatile("ldmatrix.sync.aligned.m8n8.x4.shared.b16 {%0,%1,%2,%3}, [%4];"
                 : "=r"(r0), "=r"(r1), "=r"(r2), "=r"(r3) : "r"(addr));
}
__device__ __forceinline__ void ldsm4t(uint32_t& r0, uint32_t& r1, uint32_t& r2,
                                       uint32_t& r3, uint32_t addr) {
    asm volatile("ldmatrix.sync.aligned.m8n8.x4.trans.shared.b16 {%0,%1,%2,%3}, [%4];"
                 : "=r"(r0), "=r"(r1), "=r"(r2), "=r"(r3) : "r"(addr));
}
// fp16 mma
__device__ __forceinline__ void mma16816h(float* c, uint32_t a0, uint32_t a1,
                                          uint32_t a2, uint32_t a3,
                                          uint32_t b0, uint32_t b1) {
    asm volatile(
        "mma.sync.aligned.m16n8k16.row.col.f32.f16.f16.f32 "
        "{%0,%1,%2,%3}, {%4,%5,%6,%7}, {%8,%9}, {%0,%1,%2,%3};"
        : "+f"(c[0]), "+f"(c[1]), "+f"(c[2]), "+f"(c[3])
        : "r"(a0), "r"(a1), "r"(a2), "r"(a3), "r"(b0), "r"(b1));
}

__device__ __forceinline__ uint32_t pack_f16x2(float lo, float hi) {
    __half2 p = __floats2half2_rn(lo, hi);
    return *(uint32_t*)&p;
}

// ---------------------------------------------------------------------------
// fp32 -> fp16 round; fp32 -> fp16 hi/lo split
// ---------------------------------------------------------------------------
__global__ void round_f16(const float* __restrict__ x, __half* __restrict__ h, int n4)
{
    int i = blockIdx.x * blockDim.x + threadIdx.x;
    if (i >= n4) return;
    float4 v = ((const float4*)x)[i];
    ((__half2*)h)[2*i]   = __floats2half2_rn(v.x, v.y);
    ((__half2*)h)[2*i+1] = __floats2half2_rn(v.z, v.w);
}

__global__ void split_f16(const float* __restrict__ x,
                          __half* __restrict__ hi, __half* __restrict__ lo, int n4)
{
    int i = blockIdx.x * blockDim.x + threadIdx.x;
    if (i >= n4) return;
    float4 v = ((const float4*)x)[i];
    float h0 = __half2float(__float2half_rn(v.x));
    float h1 = __half2float(__float2half_rn(v.y));
    float h2 = __half2float(__float2half_rn(v.z));
    float h3 = __half2float(__float2half_rn(v.w));
    ((__half2*)hi)[2*i]   = __floats2half2_rn(h0, h1);
    ((__half2*)hi)[2*i+1] = __floats2half2_rn(h2, h3);
    ((__half2*)lo)[2*i]   = __floats2half2_rn(v.x - h0, v.y - h1);
    ((__half2*)lo)[2*i+1] = __floats2half2_rn(v.z - h2, v.w - h3);
}

// ---------------------------------------------------------------------------
// 2-pass fp16 mma.sync GEMM (NT), 128x128 CTA tile, BK=64, 2-stage, 2 CTAs/SM.
// ---------------------------------------------------------------------------
#define BK      64
#define LDS_    72
#define PLANE_B (128 * LDS_ * 2)      // 18432
#define BUF_B   (3 * PLANE_B)         // 55296  (A | Bh | Bl)
#define GEMM_SMEM (2 * BUF_B)         // 110592 (2 CTAs/SM)

__global__ __launch_bounds__(256, 2) void gemm_2xf16(
    const __half* __restrict__ A,
    const __half* __restrict__ Bhi, const __half* __restrict__ Blo,
    float* __restrict__ C, int N, int K)
{
    extern __shared__ __align__(128) char smc[];
    const uint32_t sbase = (uint32_t)__cvta_generic_to_shared(smc);
    const int tid  = threadIdx.x;
    const int warp = tid >> 5, lane = tid & 31;
    const int bm = blockIdx.y * 128, bn = blockIdx.x * 128;
    const int wm = (warp >> 2) * 64;
    const int wn = (warp & 3) * 32;

    const __half* srcs[3] = {
        A + (size_t)bm * K, Bhi + (size_t)bn * K, Blo + (size_t)bn * K };

    const int nch = K / BK;   // 48

    auto load_chunk = [&](int kc, int bb) {
        uint32_t sb = sbase + bb * BUF_B;
        #pragma unroll
        for (int p = 0; p < 3; p++) {
            const __half* sp = srcs[p] + kc * BK;
            uint32_t pb = sb + p * PLANE_B;
            #pragma unroll
            for (int t = 0; t < 4; t++) {
                int f = tid + t * 256;        // 0..1023
                int r = f >> 3, j = f & 7;    // row 0..127, 16B chunk 0..7
                cp_async16(pb + r * (LDS_ * 2) + j * 16,
                           sp + (size_t)r * K + j * 8);
            }
        }
        CP_COMMIT();
    };

    float c[4][4][4];
    #pragma unroll
    for (int i = 0; i < 4; i++)
        #pragma unroll
        for (int j = 0; j < 4; j++)
            #pragma unroll
            for (int q = 0; q < 4; q++) c[i][j][q] = 0.f;

    load_chunk(0, 0);

    const int arow = lane & 15;
    const int ak8  = (lane >> 4) * 8;
    const int brow = (lane & 7) + ((lane >> 4) << 3);
    const int bk8  = ((lane >> 3) & 1) * 8;

    #pragma unroll 1
    for (int kc = 0; kc < nch; kc++) {
        const int bb = kc & 1;
        CP_WAIT(0);
        __syncthreads();
        if (kc + 1 < nch) load_chunk(kc + 1, bb ^ 1);

        const uint32_t sA  = sbase + bb * BUF_B;
        const uint32_t sBh = sA + PLANE_B;
        const uint32_t sBl = sA + 2 * PLANE_B;

        #pragma unroll
        for (int ks = 0; ks < 4; ks++) {
            const int k0 = ks * 16;
            uint32_t bh[4][2], bl[4][2];
            #pragma unroll
            for (int tp = 0; tp < 2; tp++) {
                uint32_t off = (uint32_t)((wn + tp*16 + brow) * LDS_ + k0 + bk8) * 2;
                ldsm4(bh[tp*2][0], bh[tp*2][1], bh[tp*2+1][0], bh[tp*2+1][1], sBh + off);
                ldsm4(bl[tp*2][0], bl[tp*2][1], bl[tp*2+1][0], bl[tp*2+1][1], sBl + off);
            }
            #pragma unroll
            for (int ti = 0; ti < 4; ti++) {
                uint32_t off = (uint32_t)((wm + ti*16 + arow) * LDS_ + k0 + ak8) * 2;
                uint32_t ah[4];
                ldsm4(ah[0], ah[1], ah[2], ah[3], sA + off);
                #pragma unroll
                for (int tj = 0; tj < 4; tj++) {
                    mma16816h(c[ti][tj], ah[0], ah[1], ah[2], ah[3],
                              bh[tj][0], bh[tj][1]);
                    mma16816h(c[ti][tj], ah[0], ah[1], ah[2], ah[3],
                              bl[tj][0], bl[tj][1]);
                }
            }
        }
    }

    const int cr = lane >> 2, cc = (lane & 3) * 2;
    #pragma unroll
    for (int ti = 0; ti < 4; ti++) {
        #pragma unroll
        for (int tj = 0; tj < 4; tj++) {
            int r0 = bm + wm + ti*16 + cr;
            int col = bn + wn + tj*8 + cc;
            *(float2*)(C + (size_t)r0 * N + col)       = make_float2(c[ti][tj][0], c[ti][tj][1]);
            *(float2*)(C + (size_t)(r0 + 8) * N + col) = make_float2(c[ti][tj][2], c[ti][tj][3]);
        }
    }
}

// ---------------------------------------------------------------------------
// RoPE: Q -> fp16 hi/lo planes (scale folded), K -> single fp16 plane.
// ---------------------------------------------------------------------------
__global__ void rope_split(const float* __restrict__ qkv,
                           __half* __restrict__ qhi, __half* __restrict__ qlo,
                           __half* __restrict__ kf)
{
    const int total = B_ * S_ * (NH + NKV) * (HD / 2);
    int i = blockIdx.x * blockDim.x + threadIdx.x;
    if (i >= total) return;
    int d    = i % (HD/2);
    int t    = i / (HD/2);
    int head = t % (NH + NKV);
    int bs   = t / (NH + NKV);
    int b    = bs / S_;
    int s    = bs % S_;

    float inv = expf(-(float)d * (logf(10000.0f) / 48.0f));
    float ang = (float)s * inv;
    float sn, cs;
    sincosf(ang, &sn, &cs);

    const float* base = qkv + (size_t)bs * QKV_W + head * HD;
    float x1 = base[d];
    float x2 = base[d + 48];
    float y1 = x1 * cs - x2 * sn;
    float y2 = x2 * cs + x1 * sn;

    if (head < NH) {
        const float scale = 0.10206207261596577f;
        y1 *= scale; y2 *= scale;
        size_t idx = ((size_t)(b * NH + head) * S_ + s) * HD;
        float h1 = __half2float(__float2half_rn(y1));
        float h2 = __half2float(__float2half_rn(y2));
        qhi[idx + d]      = __float2half_rn(h1);
        qhi[idx + d + 48] = __float2half_rn(h2);
        qlo[idx + d]      = __float2half_rn(y1 - h1);
        qlo[idx + d + 48] = __float2half_rn(y2 - h2);
    } else {
        size_t idx = ((size_t)(b * NKV + (head - NH)) * S_ + s) * HD;
        kf[idx + d]      = __float2half_rn(y1);
        kf[idx + d + 48] = __float2half_rn(y2);
    }
}

// V: fp16 hi/lo split into head-major planes.
__global__ void v_split(const float* __restrict__ qkv,
                        __half* __restrict__ vhi, __half* __restrict__ vlo)
{
    const int total = B_ * S_ * NKV * (HD / 4);
    int i = blockIdx.x * blockDim.x + threadIdx.x;
    if (i >= total) return;
    int d4  = i % (HD/4);
    int t   = i / (HD/4);
    int kvh = t % NKV;
    int bs  = t / NKV;
    int b   = bs / S_;
    int s   = bs % S_;

    const float* src = qkv + (size_t)bs * QKV_W + NH*HD + NKV*HD + kvh*HD + d4*4;
    float4 v = *(const float4*)src;
    size_t idx = ((size_t)(b * NKV + kvh) * S_ + s) * HD + d4*4;
    float h0 = __half2float(__float2half_rn(v.x));
    float h1 = __half2float(__float2half_rn(v.y));
    float h2 = __half2float(__float2half_rn(v.z));
    float h3 = __half2float(__float2half_rn(v.w));
    *(__half2*)(vhi + idx)     = __floats2half2_rn(h0, h1);
    *(__half2*)(vhi + idx + 2) = __floats2half2_rn(h2, h3);
    *(__half2*)(vlo + idx)     = __floats2half2_rn(v.x - h0, v.y - h1);
    *(__half2*)(vlo + idx + 2) = __floats2half2_rn(v.z - h2, v.w - h3);
}

// ---------------------------------------------------------------------------
// Flash attention, 2-pass fp16 mma. CTA: 128 queries x one (b,h).
// QK: (Qhi+Qlo) x Kf16 (2 passes). PV: Pf16 x (Vhi+Vlo) (2 passes).
// 8 warps x 16 rows, 64-key tiles, 3-stage KV ring (3 planes: K|Vh|Vl).
// ---------------------------------------------------------------------------
#define ALDS   104
#define QBYTES (128 * ALDS * 2)         // 26624
#define KVTILE (64 * ALDS * 2)          // 13312
#define KVBUF  (3 * KVTILE)             // 39936
#define ASTAGES 3
#define ATT_SMEM (2*QBYTES + ASTAGES*KVBUF)   // 173056

__global__ __launch_bounds__(256, 1) void attn_mma(
    const __half* __restrict__ qhi, const __half* __restrict__ qlo,
    const __half* __restrict__ kf,
    const __half* __restrict__ vhi, const __half* __restrict__ vlo,
    __half* __restrict__ aout)
{
    extern __shared__ __align__(128) char smc[];
    const uint32_t sb  = (uint32_t)__cvta_generic_to_shared(smc);
    const uint32_t sQh = sb, sQl = sb + QBYTES;
    const uint32_t sKV = sb + 2 * QBYTES;

    const int tid  = threadIdx.x;
    const int warp = tid >> 5, lane = tid & 31;
    const int qt = blockIdx.x;
    const int bh = blockIdx.y;
    const int b  = bh >> 5, h = bh & 31, kvh = h >> 2;
    const int q0 = qt * 128;
    const int wm = warp * 16;

    const __half* qsh = qhi + ((size_t)(b*NH + h) * S_ + q0) * HD;
    const __half* qsl = qlo + ((size_t)(b*NH + h) * S_ + q0) * HD;
    const __half* ksf = kf  + (size_t)(b*NKV + kvh) * S_ * HD;
    const __half* vsh = vhi + (size_t)(b*NKV + kvh) * S_ * HD;
    const __half* vsl = vlo + (size_t)(b*NKV + kvh) * S_ * HD;

    #pragma unroll
    for (int u = 0; u < 6; u++) {
        int f = tid + u * 256;
        int r = f / 12, cidx = f % 12;
        cp_async16(sQh + r * (ALDS*2) + cidx * 16, qsh + (size_t)r * HD + cidx * 8);
        cp_async16(sQl + r * (ALDS*2) + cidx * 16, qsl + (size_t)r * HD + cidx * 8);
    }

    auto load_kv = [&](int kt, int bb) {
        uint32_t base = sKV + bb * KVBUF;
        int k0 = kt * 64;
        #pragma unroll
        for (int u = 0; u < 3; u++) {
            int f = tid + u * 256;
            int r = f / 12, cidx = f % 12;
            size_t g = (size_t)(k0 + r) * HD + cidx * 8;
            uint32_t o = r * (ALDS*2) + cidx * 16;
            cp_async16(base + 0*KVTILE + o, ksf + g);
            cp_async16(base + 1*KVTILE + o, vsh + g);
            cp_async16(base + 2*KVTILE + o, vsl + g);
        }
        CP_COMMIT();
    };

    const int nkt = 2 * qt + 2;
    load_kv(0, 0);
    if (nkt > 1) load_kv(1, 1); else CP_COMMIT();

    const int arow = lane & 15;
    const int ak8  = (lane >> 4) * 8;
    const int brow = (lane & 7) + ((lane >> 4) << 3);
    const int bk8  = ((lane >> 3) & 1) * 8;
    const int vrow = lane & 15;
    const int vn8  = (lane >> 4) * 8;
    const int r_   = lane >> 2;
    const int c2_  = (lane & 3) * 2;

    float o[12][4];
    #pragma unroll
    for (int t = 0; t < 12; t++)
        #pragma unroll
        for (int q = 0; q < 4; q++) o[t][q] = 0.f;
    float m0 = -1e30f, m1 = -1e30f, l0 = 0.f, l1 = 0.f;

    const int row_g0 = q0 + wm + r_;
    const int wmax   = q0 + wm + 15;

    int bb = 0;
    #pragma unroll 1
    for (int kt = 0; kt < nkt; kt++) {
        const int k0 = kt * 64;
        CP_WAIT(1);
        __syncthreads();
        if (kt + 2 < nkt) {
            int nb = bb + 2; if (nb >= ASTAGES) nb -= ASTAGES;
            load_kv(kt + 2, nb);
        } else CP_COMMIT();

        if (k0 <= wmax) {
            const uint32_t sK  = sKV + bb * KVBUF;
            const uint32_t sVh = sK + KVTILE;
            const uint32_t sVl = sK + 2 * KVTILE;

            float s[8][4];
            #pragma unroll
            for (int t = 0; t < 8; t++)
                #pragma unroll
                for (int q = 0; q < 4; q++) s[t][q] = 0.f;

            #pragma unroll
            for (int ks = 0; ks < 6; ks++) {
                uint32_t aoff = (uint32_t)((wm + arow) * ALDS + ks*16 + ak8) * 2;
                uint32_t ah[4], al[4];
                ldsm4(ah[0], ah[1], ah[2], ah[3], sQh + aoff);
                ldsm4(al[0], al[1], al[2], al[3], sQl + aoff);
                #pragma unroll
                for (int np = 0; np < 4; np++) {
                    uint32_t boff = (uint32_t)((np*16 + brow) * ALDS + ks*16 + bk8) * 2;
                    uint32_t kh_[4];
                    ldsm4(kh_[0], kh_[1], kh_[2], kh_[3], sK + boff);
                    mma16816h(s[2*np],   ah[0],ah[1],ah[2],ah[3], kh_[0], kh_[1]);
                    mma16816h(s[2*np],   al[0],al[1],al[2],al[3], kh_[0], kh_[1]);
                    mma16816h(s[2*np+1], ah[0],ah[1],ah[2],ah[3], kh_[2], kh_[3]);
                    mma16816h(s[2*np+1], al[0],al[1],al[2],al[3], kh_[2], kh_[3]);
                }
            }

            if (k0 + 63 > q0 + wm) {
                #pragma unroll
                for (int t = 0; t < 8; t++) {
                    int col = k0 + t*8 + c2_;
                    if (col     > row_g0)     s[t][0] = -1e30f;
                    if (col + 1 > row_g0)     s[t][1] = -1e30f;
                    if (col     > row_g0 + 8) s[t][2] = -1e30f;
                    if (col + 1 > row_g0 + 8) s[t][3] = -1e30f;
                }
            }

            float mx0 = -1e30f, mx1 = -1e30f;
            #pragma unroll
            for (int t = 0; t < 8; t++) {
                mx0 = fmaxf(mx0, fmaxf(s[t][0], s[t][1]));
                mx1 = fmaxf(mx1, fmaxf(s[t][2], s[t][3]));
            }
            mx0 = fmaxf(mx0, __shfl_xor_sync(0xffffffff, mx0, 1));
            mx0 = fmaxf(mx0, __shfl_xor_sync(0xffffffff, mx0, 2));
            mx1 = fmaxf(mx1, __shfl_xor_sync(0xffffffff, mx1, 1));
            mx1 = fmaxf(mx1, __shfl_xor_sync(0xffffffff, mx1, 2));

            float mn0 = fmaxf(m0, mx0), mn1 = fmaxf(m1, mx1);
            float al0 = __expf(m0 - mn0), al1 = __expf(m1 - mn1);
            m0 = mn0; m1 = mn1;

            float sum0 = 0.f, sum1 = 0.f;
            #pragma unroll
            for (int t = 0; t < 8; t++) {
                s[t][0] = __expf(s[t][0] - m0);
                s[t][1] = __expf(s[t][1] - m0);
                s[t][2] = __expf(s[t][2] - m1);
                s[t][3] = __expf(s[t][3] - m1);
                sum0 += s[t][0] + s[t][1];
                sum1 += s[t][2] + s[t][3];
            }
            sum0 += __shfl_xor_sync(0xffffffff, sum0, 1);
            sum0 += __shfl_xor_sync(0xffffffff, sum0, 2);
            sum1 += __shfl_xor_sync(0xffffffff, sum1, 1);
            sum1 += __shfl_xor_sync(0xffffffff, sum1, 2);
            l0 = l0 * al0 + sum0;
            l1 = l1 * al1 + sum1;

            #pragma unroll
            for (int t = 0; t < 12; t++) {
                o[t][0] *= al0; o[t][1] *= al0;
                o[t][2] *= al1; o[t][3] *= al1;
            }

            #pragma unroll
            for (int ks = 0; ks < 4; ks++) {
                const int j0 = 2*ks, j1 = 2*ks + 1;
                uint32_t ph[4];
                ph[0] = pack_f16x2(s[j0][0], s[j0][1]);
                ph[1] = pack_f16x2(s[j0][2], s[j0][3]);
                ph[2] = pack_f16x2(s[j1][0], s[j1][1]);
                ph[3] = pack_f16x2(s[j1][2], s[j1][3]);
                #pragma unroll
                for (int np = 0; np < 6; np++) {
                    uint32_t voff = (uint32_t)((ks*16 + vrow) * ALDS + np*16 + vn8) * 2;
                    uint32_t vh_[4], vl_[4];
                    ldsm4t(vh_[0], vh_[1], vh_[2], vh_[3], sVh + voff);
                    ldsm4t(vl_[0], vl_[1], vl_[2], vl_[3], sVl + voff);
                    mma16816h(o[2*np],   ph[0],ph[1],ph[2],ph[3], vh_[0], vh_[1]);
                    mma16816h(o[2*np],   ph[0],ph[1],ph[2],ph[3], vl_[0], vl_[1]);
                    mma16816h(o[2*np+1], ph[0],ph[1],ph[2],ph[3], vh_[2], vh_[3]);
                    mma16816h(o[2*np+1], ph[0],ph[1],ph[2],ph[3], vl_[2], vl_[3]);
                }
            }
        }
        if (++bb == ASTAGES) bb = 0;
    }

    const float il0 = 1.f / l0, il1 = 1.f / l1;
    const size_t mrow0 = (size_t)(b * S_ + row_g0) * H_;
    const size_t mrow1 = mrow0 + 8 * (size_t)H_;
    #pragma unroll
    for (int t = 0; t < 12; t++) {
        int col = h * HD + t*8 + c2_;
        *(uint32_t*)(aout + mrow0 + col) = pack_f16x2(o[t][0]*il0, o[t][1]*il0);
        *(uint32_t*)(aout + mrow1 + col) = pack_f16x2(o[t][2]*il1, o[t][3]*il1);
    }
}

// ---------------------------------------------------------------------------

extern "C" void kernel_launch(void* const* d_in, const int* in_sizes, int n_in,
                              void* d_out, int out_size)
{
    const float* hidden = (const float*)d_in[0];
    const float* w_qkv  = (const float*)d_in[2];
    const float* w_o    = (const float*)d_in[3];
    float* out = (float*)d_out;

    float *qkv;
    __half *h_f16, *wq_hi, *wq_lo, *wo_hi, *wo_lo, *a_f16;
    __half *q_hi, *q_lo, *k_f16, *v_hi, *v_lo;
    cudaGetSymbolAddress((void**)&qkv,   g_qkv);
    cudaGetSymbolAddress((void**)&h_f16, g_h_f16);
    cudaGetSymbolAddress((void**)&wq_hi, g_wq_hi);
    cudaGetSymbolAddress((void**)&wq_lo, g_wq_lo);
    cudaGetSymbolAddress((void**)&wo_hi, g_wo_hi);
    cudaGetSymbolAddress((void**)&wo_lo, g_wo_lo);
    cudaGetSymbolAddress((void**)&a_f16, g_a_f16);
    cudaGetSymbolAddress((void**)&q_hi,  g_q_hi);
    cudaGetSymbolAddress((void**)&q_lo,  g_q_lo);
    cudaGetSymbolAddress((void**)&k_f16, g_k_f16);
    cudaGetSymbolAddress((void**)&v_hi,  g_v_hi);
    cudaGetSymbolAddress((void**)&v_lo,  g_v_lo);

    cudaFuncSetAttribute(gemm_2xf16, cudaFuncAttributeMaxDynamicSharedMemorySize, GEMM_SMEM);
    cudaFuncSetAttribute(attn_mma,   cudaFuncAttributeMaxDynamicSharedMemorySize, ATT_SMEM);

    {
        int n4;
        n4 = (M_ * H_) / 4;
        round_f16<<<(n4 + 255)/256, 256>>>(hidden, h_f16, n4);
        n4 = (QKV_W * H_) / 4;
        split_f16<<<(n4 + 255)/256, 256>>>(w_qkv, wq_hi, wq_lo, n4);
        n4 = (H_ * H_) / 4;
        split_f16<<<(n4 + 255)/256, 256>>>(w_o, wo_hi, wo_lo, n4);
    }

    gemm_2xf16<<<dim3(QKV_W/128, M_/128), 256, GEMM_SMEM>>>(
        h_f16, wq_hi, wq_lo, qkv, QKV_W, H_);

    {
        int total = B_ * S_ * (NH + NKV) * (HD/2);
        rope_split<<<(total + 255)/256, 256>>>(qkv, q_hi, q_lo, k_f16);
        int vt = B_ * S_ * NKV * (HD/4);
        v_split<<<(vt + 255)/256, 256>>>(qkv, v_hi, v_lo);
    }

    attn_mma<<<dim3(S_/128, B_*NH), 256, ATT_SMEM>>>(
        q_hi, q_lo, k_f16, v_hi, v_lo, a_f16);

    gemm_2xf16<<<dim3(H_/128, M_/128), 256, GEMM_SMEM>>>(
        a_f16, wo_hi, wo_lo, out, H_, H_);
}

// round 10
// speedup vs baseline: 1.5331x; 1.0005x over previous
#include <cuda_runtime.h>
#include <cuda_bf16.h>
#include <cuda_fp16.h>
#include <math.h>
#include <stdint.h>

#define B_   2
#define S_   2048
#define H_   3072
#define NH   32
#define NKV  8
#define HD   96
#define QKV_W (NH*HD + 2*NKV*HD)   // 4608
#define M_   (B_*S_)               // 4096

// ---------------- scratch (device globals: allocation-free rule) -----------
__device__ float g_qkv[(size_t)M_ * QKV_W];
__device__ __half g_h_f16[(size_t)M_ * H_];
__device__ __half g_wq_hi[(size_t)QKV_W * H_], g_wq_lo[(size_t)QKV_W * H_];
__device__ __half g_wo_hi[(size_t)H_ * H_],    g_wo_lo[(size_t)H_ * H_];
__device__ __half g_a_f16[(size_t)M_ * H_];
__device__ __half g_q_hi[(size_t)B_*NH*S_*HD],  g_q_lo[(size_t)B_*NH*S_*HD];
__device__ __half g_k_f16[(size_t)B_*NKV*S_*HD];
__device__ __half g_v_hi[(size_t)B_*NKV*S_*HD], g_v_lo[(size_t)B_*NKV*S_*HD];

// ---------------- base-target PTX helpers ----------------------------------
__device__ __forceinline__ void cp_async16(uint32_t dst, const void* src) {
    asm volatile("cp.async.cg.shared.global [%0], [%1], 16;"
                 :: "r"(dst), "l"(src) : "memory");
}
#define CP_COMMIT() asm volatile("cp.async.commit_group;" ::: "memory")
#define CP_WAIT(n)  asm volatile("cp.async.wait_group %0;" :: "n"(n) : "memory")

__device__ __forceinline__ void ldsm4(uint32_t& r0, uint32_t& r1, uint32_t& r2,
                                      uint32_t& r3, uint32_t addr) {
    asm volatile("ldmatrix.sync.aligned.m8n8.x4.shared.b16 {%0,%1,%2,%3}, [%4];"
                 : "=r"(r0), "=r"(r1), "=r"(r2), "=r"(r3) : "r"(addr));
}
__device__ __forceinline__ void ldsm4t(uint32_t& r0, uint32_t& r1, uint32_t& r2,
                                       uint32_t& r3, uint32_t addr) {
    asm volatile("ldmatrix.sync.aligned.m8n8.x4.trans.shared.b16 {%0,%1,%2,%3}, [%4];"
                 : "=r"(r0), "=r"(r1), "=r"(r2), "=r"(r3) : "r"(addr));
}
// fp16 mma
__device__ __forceinline__ void mma16816h(float* c, uint32_t a0, uint32_t a1,
                                          uint32_t a2, uint32_t a3,
                                          uint32_t b0, uint32_t b1) {
    asm volatile(
        "mma.sync.aligned.m16n8k16.row.col.f32.f16.f16.f32 "
        "{%0,%1,%2,%3}, {%4,%5,%6,%7}, {%8,%9}, {%0,%1,%2,%3};"
        : "+f"(c[0]), "+f"(c[1]), "+f"(c[2]), "+f"(c[3])
        : "r"(a0), "r"(a1), "r"(a2), "r"(a3), "r"(b0), "r"(b1));
}

__device__ __forceinline__ uint32_t pack_f16x2(float lo, float hi) {
    __half2 p = __floats2half2_rn(lo, hi);
    return *(uint32_t*)&p;
}

// ---------------------------------------------------------------------------
// fp32 -> fp16 round; fp32 -> fp16 hi/lo split
// ---------------------------------------------------------------------------
__global__ void round_f16(const float* __restrict__ x, __half* __restrict__ h, int n4)
{
    int i = blockIdx.x * blockDim.x + threadIdx.x;
    if (i >= n4) return;
    float4 v = ((const float4*)x)[i];
    ((__half2*)h)[2*i]   = __floats2half2_rn(v.x, v.y);
    ((__half2*)h)[2*i+1] = __floats2half2_rn(v.z, v.w);
}

__global__ void split_f16(const float* __restrict__ x,
                          __half* __restrict__ hi, __half* __restrict__ lo, int n4)
{
    int i = blockIdx.x * blockDim.x + threadIdx.x;
    if (i >= n4) return;
    float4 v = ((const float4*)x)[i];
    float h0 = __half2float(__float2half_rn(v.x));
    float h1 = __half2float(__float2half_rn(v.y));
    float h2 = __half2float(__float2half_rn(v.z));
    float h3 = __half2float(__float2half_rn(v.w));
    ((__half2*)hi)[2*i]   = __floats2half2_rn(h0, h1);
    ((__half2*)hi)[2*i+1] = __floats2half2_rn(h2, h3);
    ((__half2*)lo)[2*i]   = __floats2half2_rn(v.x - h0, v.y - h1);
    ((__half2*)lo)[2*i+1] = __floats2half2_rn(v.z - h2, v.w - h3);
}

// ---------------------------------------------------------------------------
// 2-pass fp16 mma.sync GEMM (NT), 128x128 CTA tile, BK=64, 2-stage, 2 CTAs/SM.
// Inner mma order: pass-major per A-fragment (dependency distance 4).
// ---------------------------------------------------------------------------
#define BK      64
#define LDS_    72
#define PLANE_B (128 * LDS_ * 2)      // 18432
#define BUF_B   (3 * PLANE_B)         // 55296
#define GEMM_SMEM (2 * BUF_B)         // 110592

__global__ __launch_bounds__(256, 2) void gemm_2xf16(
    const __half* __restrict__ A,
    const __half* __restrict__ Bhi, const __half* __restrict__ Blo,
    float* __restrict__ C, int N, int K)
{
    extern __shared__ __align__(128) char smc[];
    const uint32_t sbase = (uint32_t)__cvta_generic_to_shared(smc);
    const int tid  = threadIdx.x;
    const int warp = tid >> 5, lane = tid & 31;
    const int bm = blockIdx.y * 128, bn = blockIdx.x * 128;
    const int wm = (warp >> 2) * 64;
    const int wn = (warp & 3) * 32;

    const __half* srcs[3] = {
        A + (size_t)bm * K, Bhi + (size_t)bn * K, Blo + (size_t)bn * K };

    const int nch = K / BK;

    auto load_chunk = [&](int kc, int bb) {
        uint32_t sb = sbase + bb * BUF_B;
        #pragma unroll
        for (int p = 0; p < 3; p++) {
            const __half* sp = srcs[p] + kc * BK;
            uint32_t pb = sb + p * PLANE_B;
            #pragma unroll
            for (int t = 0; t < 4; t++) {
                int f = tid + t * 256;
                int r = f >> 3, j = f & 7;
                cp_async16(pb + r * (LDS_ * 2) + j * 16,
                           sp + (size_t)r * K + j * 8);
            }
        }
        CP_COMMIT();
    };

    float c[4][4][4];
    #pragma unroll
    for (int i = 0; i < 4; i++)
        #pragma unroll
        for (int j = 0; j < 4; j++)
            #pragma unroll
            for (int q = 0; q < 4; q++) c[i][j][q] = 0.f;

    load_chunk(0, 0);

    const int arow = lane & 15;
    const int ak8  = (lane >> 4) * 8;
    const int brow = (lane & 7) + ((lane >> 4) << 3);
    const int bk8  = ((lane >> 3) & 1) * 8;

    #pragma unroll 1
    for (int kc = 0; kc < nch; kc++) {
        const int bb = kc & 1;
        CP_WAIT(0);
        __syncthreads();
        if (kc + 1 < nch) load_chunk(kc + 1, bb ^ 1);

        const uint32_t sA  = sbase + bb * BUF_B;
        const uint32_t sBh = sA + PLANE_B;
        const uint32_t sBl = sA + 2 * PLANE_B;

        #pragma unroll
        for (int ks = 0; ks < 4; ks++) {
            const int k0 = ks * 16;
            uint32_t bh[4][2], bl[4][2];
            #pragma unroll
            for (int tp = 0; tp < 2; tp++) {
                uint32_t off = (uint32_t)((wn + tp*16 + brow) * LDS_ + k0 + bk8) * 2;
                ldsm4(bh[tp*2][0], bh[tp*2][1], bh[tp*2+1][0], bh[tp*2+1][1], sBh + off);
                ldsm4(bl[tp*2][0], bl[tp*2][1], bl[tp*2+1][0], bl[tp*2+1][1], sBl + off);
            }
            #pragma unroll
            for (int ti = 0; ti < 4; ti++) {
                uint32_t off = (uint32_t)((wm + ti*16 + arow) * LDS_ + k0 + ak8) * 2;
                uint32_t ah[4];
                ldsm4(ah[0], ah[1], ah[2], ah[3], sA + off);
                // pass-major: 4 independent accumulators per pass (distance 4)
                mma16816h(c[ti][0], ah[0], ah[1], ah[2], ah[3], bh[0][0], bh[0][1]);
                mma16816h(c[ti][1], ah[0], ah[1], ah[2], ah[3], bh[1][0], bh[1][1]);
                mma16816h(c[ti][2], ah[0], ah[1], ah[2], ah[3], bh[2][0], bh[2][1]);
                mma16816h(c[ti][3], ah[0], ah[1], ah[2], ah[3], bh[3][0], bh[3][1]);
                mma16816h(c[ti][0], ah[0], ah[1], ah[2], ah[3], bl[0][0], bl[0][1]);
                mma16816h(c[ti][1], ah[0], ah[1], ah[2], ah[3], bl[1][0], bl[1][1]);
                mma16816h(c[ti][2], ah[0], ah[1], ah[2], ah[3], bl[2][0], bl[2][1]);
                mma16816h(c[ti][3], ah[0], ah[1], ah[2], ah[3], bl[3][0], bl[3][1]);
            }
        }
    }

    const int cr = lane >> 2, cc = (lane & 3) * 2;
    #pragma unroll
    for (int ti = 0; ti < 4; ti++) {
        #pragma unroll
        for (int tj = 0; tj < 4; tj++) {
            int r0 = bm + wm + ti*16 + cr;
            int col = bn + wn + tj*8 + cc;
            *(float2*)(C + (size_t)r0 * N + col)       = make_float2(c[ti][tj][0], c[ti][tj][1]);
            *(float2*)(C + (size_t)(r0 + 8) * N + col) = make_float2(c[ti][tj][2], c[ti][tj][3]);
        }
    }
}

// ---------------------------------------------------------------------------
// RoPE: Q -> fp16 hi/lo planes (scale folded), K -> single fp16 plane.
// ---------------------------------------------------------------------------
__global__ void rope_split(const float* __restrict__ qkv,
                           __half* __restrict__ qhi, __half* __restrict__ qlo,
                           __half* __restrict__ kf)
{
    const int total = B_ * S_ * (NH + NKV) * (HD / 2);
    int i = blockIdx.x * blockDim.x + threadIdx.x;
    if (i >= total) return;
    int d    = i % (HD/2);
    int t    = i / (HD/2);
    int head = t % (NH + NKV);
    int bs   = t / (NH + NKV);
    int b    = bs / S_;
    int s    = bs % S_;

    float inv = expf(-(float)d * (logf(10000.0f) / 48.0f));
    float ang = (float)s * inv;
    float sn, cs;
    sincosf(ang, &sn, &cs);

    const float* base = qkv + (size_t)bs * QKV_W + head * HD;
    float x1 = base[d];
    float x2 = base[d + 48];
    float y1 = x1 * cs - x2 * sn;
    float y2 = x2 * cs + x1 * sn;

    if (head < NH) {
        const float scale = 0.10206207261596577f;
        y1 *= scale; y2 *= scale;
        size_t idx = ((size_t)(b * NH + head) * S_ + s) * HD;
        float h1 = __half2float(__float2half_rn(y1));
        float h2 = __half2float(__float2half_rn(y2));
        qhi[idx + d]      = __float2half_rn(h1);
        qhi[idx + d + 48] = __float2half_rn(h2);
        qlo[idx + d]      = __float2half_rn(y1 - h1);
        qlo[idx + d + 48] = __float2half_rn(y2 - h2);
    } else {
        size_t idx = ((size_t)(b * NKV + (head - NH)) * S_ + s) * HD;
        kf[idx + d]      = __float2half_rn(y1);
        kf[idx + d + 48] = __float2half_rn(y2);
    }
}

__global__ void v_split(const float* __restrict__ qkv,
                        __half* __restrict__ vhi, __half* __restrict__ vlo)
{
    const int total = B_ * S_ * NKV * (HD / 4);
    int i = blockIdx.x * blockDim.x + threadIdx.x;
    if (i >= total) return;
    int d4  = i % (HD/4);
    int t   = i / (HD/4);
    int kvh = t % NKV;
    int bs  = t / NKV;
    int b   = bs / S_;
    int s   = bs % S_;

    const float* src = qkv + (size_t)bs * QKV_W + NH*HD + NKV*HD + kvh*HD + d4*4;
    float4 v = *(const float4*)src;
    size_t idx = ((size_t)(b * NKV + kvh) * S_ + s) * HD + d4*4;
    float h0 = __half2float(__float2half_rn(v.x));
    float h1 = __half2float(__float2half_rn(v.y));
    float h2 = __half2float(__float2half_rn(v.z));
    float h3 = __half2float(__float2half_rn(v.w));
    *(__half2*)(vhi + idx)     = __floats2half2_rn(h0, h1);
    *(__half2*)(vhi + idx + 2) = __floats2half2_rn(h2, h3);
    *(__half2*)(vlo + idx)     = __floats2half2_rn(v.x - h0, v.y - h1);
    *(__half2*)(vlo + idx + 2) = __floats2half2_rn(v.z - h2, v.w - h3);
}

// ---------------------------------------------------------------------------
// Flash attention, 2-pass fp16 mma. CTA: 128 queries x one (b,h).
// QK: (Qhi+Qlo) x Kf16. PV: Pf16 x (Vhi+Vlo). 8 warps x 16 rows,
// 64-key tiles, 3-stage KV ring. MMA order maximizes accumulator distance.
// ---------------------------------------------------------------------------
#define ALDS   104
#define QBYTES (128 * ALDS * 2)         // 26624
#define KVTILE (64 * ALDS * 2)          // 13312
#define KVBUF  (3 * KVTILE)             // 39936
#define ASTAGES 3
#define ATT_SMEM (2*QBYTES + ASTAGES*KVBUF)   // 173056

__global__ __launch_bounds__(256, 1) void attn_mma(
    const __half* __restrict__ qhi, const __half* __restrict__ qlo,
    const __half* __restrict__ kf,
    const __half* __restrict__ vhi, const __half* __restrict__ vlo,
    __half* __restrict__ aout)
{
    extern __shared__ __align__(128) char smc[];
    const uint32_t sb  = (uint32_t)__cvta_generic_to_shared(smc);
    const uint32_t sQh = sb, sQl = sb + QBYTES;
    const uint32_t sKV = sb + 2 * QBYTES;

    const int tid  = threadIdx.x;
    const int warp = tid >> 5, lane = tid & 31;
    const int qt = blockIdx.x;
    const int bh = blockIdx.y;
    const int b  = bh >> 5, h = bh & 31, kvh = h >> 2;
    const int q0 = qt * 128;
    const int wm = warp * 16;

    const __half* qsh = qhi + ((size_t)(b*NH + h) * S_ + q0) * HD;
    const __half* qsl = qlo + ((size_t)(b*NH + h) * S_ + q0) * HD;
    const __half* ksf = kf  + (size_t)(b*NKV + kvh) * S_ * HD;
    const __half* vsh = vhi + (size_t)(b*NKV + kvh) * S_ * HD;
    const __half* vsl = vlo + (size_t)(b*NKV + kvh) * S_ * HD;

    #pragma unroll
    for (int u = 0; u < 6; u++) {
        int f = tid + u * 256;
        int r = f / 12, cidx = f % 12;
        cp_async16(sQh + r * (ALDS*2) + cidx * 16, qsh + (size_t)r * HD + cidx * 8);
        cp_async16(sQl + r * (ALDS*2) + cidx * 16, qsl + (size_t)r * HD + cidx * 8);
    }

    auto load_kv = [&](int kt, int bb) {
        uint32_t base = sKV + bb * KVBUF;
        int k0 = kt * 64;
        #pragma unroll
        for (int u = 0; u < 3; u++) {
            int f = tid + u * 256;
            int r = f / 12, cidx = f % 12;
            size_t g = (size_t)(k0 + r) * HD + cidx * 8;
            uint32_t o = r * (ALDS*2) + cidx * 16;
            cp_async16(base + 0*KVTILE + o, ksf + g);
            cp_async16(base + 1*KVTILE + o, vsh + g);
            cp_async16(base + 2*KVTILE + o, vsl + g);
        }
        CP_COMMIT();
    };

    const int nkt = 2 * qt + 2;
    load_kv(0, 0);
    if (nkt > 1) load_kv(1, 1); else CP_COMMIT();

    const int arow = lane & 15;
    const int ak8  = (lane >> 4) * 8;
    const int brow = (lane & 7) + ((lane >> 4) << 3);
    const int bk8  = ((lane >> 3) & 1) * 8;
    const int vrow = lane & 15;
    const int vn8  = (lane >> 4) * 8;
    const int r_   = lane >> 2;
    const int c2_  = (lane & 3) * 2;

    float o[12][4];
    #pragma unroll
    for (int t = 0; t < 12; t++)
        #pragma unroll
        for (int q = 0; q < 4; q++) o[t][q] = 0.f;
    float m0 = -1e30f, m1 = -1e30f, l0 = 0.f, l1 = 0.f;

    const int row_g0 = q0 + wm + r_;
    const int wmax   = q0 + wm + 15;

    int bb = 0;
    #pragma unroll 1
    for (int kt = 0; kt < nkt; kt++) {
        const int k0 = kt * 64;
        CP_WAIT(1);
        __syncthreads();
        if (kt + 2 < nkt) {
            int nb = bb + 2; if (nb >= ASTAGES) nb -= ASTAGES;
            load_kv(kt + 2, nb);
        } else CP_COMMIT();

        if (k0 <= wmax) {
            const uint32_t sK  = sKV + bb * KVBUF;
            const uint32_t sVh = sK + KVTILE;
            const uint32_t sVl = sK + 2 * KVTILE;

            float s[8][4];
            #pragma unroll
            for (int t = 0; t < 8; t++)
                #pragma unroll
                for (int q = 0; q < 4; q++) s[t][q] = 0.f;

            #pragma unroll
            for (int ks = 0; ks < 6; ks++) {
                uint32_t aoff = (uint32_t)((wm + arow) * ALDS + ks*16 + ak8) * 2;
                uint32_t ah[4], al[4];
                ldsm4(ah[0], ah[1], ah[2], ah[3], sQh + aoff);
                ldsm4(al[0], al[1], al[2], al[3], sQl + aoff);
                // preload all K fragments for this k-step (16 regs)
                uint32_t kh_[4][4];
                #pragma unroll
                for (int np = 0; np < 4; np++) {
                    uint32_t boff = (uint32_t)((np*16 + brow) * ALDS + ks*16 + bk8) * 2;
                    ldsm4(kh_[np][0], kh_[np][1], kh_[np][2], kh_[np][3], sK + boff);
                }
                // hi pass: 8 independent accumulators, then lo pass (distance 8)
                #pragma unroll
                for (int np = 0; np < 4; np++) {
                    mma16816h(s[2*np],   ah[0],ah[1],ah[2],ah[3], kh_[np][0], kh_[np][1]);
                    mma16816h(s[2*np+1], ah[0],ah[1],ah[2],ah[3], kh_[np][2], kh_[np][3]);
                }
                #pragma unroll
                for (int np = 0; np < 4; np++) {
                    mma16816h(s[2*np],   al[0],al[1],al[2],al[3], kh_[np][0], kh_[np][1]);
                    mma16816h(s[2*np+1], al[0],al[1],al[2],al[3], kh_[np][2], kh_[np][3]);
                }
            }

            if (k0 + 63 > q0 + wm) {
                #pragma unroll
                for (int t = 0; t < 8; t++) {
                    int col = k0 + t*8 + c2_;
                    if (col     > row_g0)     s[t][0] = -1e30f;
                    if (col + 1 > row_g0)     s[t][1] = -1e30f;
                    if (col     > row_g0 + 8) s[t][2] = -1e30f;
                    if (col + 1 > row_g0 + 8) s[t][3] = -1e30f;
                }
            }

            float mx0 = -1e30f, mx1 = -1e30f;
            #pragma unroll
            for (int t = 0; t < 8; t++) {
                mx0 = fmaxf(mx0, fmaxf(s[t][0], s[t][1]));
                mx1 = fmaxf(mx1, fmaxf(s[t][2], s[t][3]));
            }
            mx0 = fmaxf(mx0, __shfl_xor_sync(0xffffffff, mx0, 1));
            mx0 = fmaxf(mx0, __shfl_xor_sync(0xffffffff, mx0, 2));
            mx1 = fmaxf(mx1, __shfl_xor_sync(0xffffffff, mx1, 1));
            mx1 = fmaxf(mx1, __shfl_xor_sync(0xffffffff, mx1, 2));

            float mn0 = fmaxf(m0, mx0), mn1 = fmaxf(m1, mx1);
            float al0 = __expf(m0 - mn0), al1 = __expf(m1 - mn1);
            m0 = mn0; m1 = mn1;

            float sum0 = 0.f, sum1 = 0.f;
            #pragma unroll
            for (int t = 0; t < 8; t++) {
                s[t][0] = __expf(s[t][0] - m0);
                s[t][1] = __expf(s[t][1] - m0);
                s[t][2] = __expf(s[t][2] - m1);
                s[t][3] = __expf(s[t][3] - m1);
                sum0 += s[t][0] + s[t][1];
                sum1 += s[t][2] + s[t][3];
            }
            sum0 += __shfl_xor_sync(0xffffffff, sum0, 1);
            sum0 += __shfl_xor_sync(0xffffffff, sum0, 2);
            sum1 += __shfl_xor_sync(0xffffffff, sum1, 1);
            sum1 += __shfl_xor_sync(0xffffffff, sum1, 2);
            l0 = l0 * al0 + sum0;
            l1 = l1 * al1 + sum1;

            #pragma unroll
            for (int t = 0; t < 12; t++) {
                o[t][0] *= al0; o[t][1] *= al0;
                o[t][2] *= al1; o[t][3] *= al1;
            }

            #pragma unroll
            for (int ks = 0; ks < 4; ks++) {
                const int j0 = 2*ks, j1 = 2*ks + 1;
                uint32_t ph[4];
                ph[0] = pack_f16x2(s[j0][0], s[j0][1]);
                ph[1] = pack_f16x2(s[j0][2], s[j0][3]);
                ph[2] = pack_f16x2(s[j1][0], s[j1][1]);
                ph[3] = pack_f16x2(s[j1][2], s[j1][3]);
                // process V n-tiles in pairs: hi pass over 4 accs, then lo pass
                #pragma unroll
                for (int npp = 0; npp < 3; npp++) {
                    const int np = 2 * npp;
                    uint32_t voffa = (uint32_t)((ks*16 + vrow) * ALDS + np*16 + vn8) * 2;
                    uint32_t voffb = (uint32_t)((ks*16 + vrow) * ALDS + (np+1)*16 + vn8) * 2;
                    uint32_t vha[4], vhb[4], vla[4], vlb[4];
                    ldsm4t(vha[0], vha[1], vha[2], vha[3], sVh + voffa);
                    ldsm4t(vhb[0], vhb[1], vhb[2], vhb[3], sVh + voffb);
                    ldsm4t(vla[0], vla[1], vla[2], vla[3], sVl + voffa);
                    ldsm4t(vlb[0], vlb[1], vlb[2], vlb[3], sVl + voffb);
                    mma16816h(o[2*np],   ph[0],ph[1],ph[2],ph[3], vha[0], vha[1]);
                    mma16816h(o[2*np+1], ph[0],ph[1],ph[2],ph[3], vha[2], vha[3]);
                    mma16816h(o[2*np+2], ph[0],ph[1],ph[2],ph[3], vhb[0], vhb[1]);
                    mma16816h(o[2*np+3], ph[0],ph[1],ph[2],ph[3], vhb[2], vhb[3]);
                    mma16816h(o[2*np],   ph[0],ph[1],ph[2],ph[3], vla[0], vla[1]);
                    mma16816h(o[2*np+1], ph[0],ph[1],ph[2],ph[3], vla[2], vla[3]);
                    mma16816h(o[2*np+2], ph[0],ph[1],ph[2],ph[3], vlb[0], vlb[1]);
                    mma16816h(o[2*np+3], ph[0],ph[1],ph[2],ph[3], vlb[2], vlb[3]);
                }
            }
        }
        if (++bb == ASTAGES) bb = 0;
    }

    const float il0 = 1.f / l0, il1 = 1.f / l1;
    const size_t mrow0 = (size_t)(b * S_ + row_g0) * H_;
    const size_t mrow1 = mrow0 + 8 * (size_t)H_;
    #pragma unroll
    for (int t = 0; t < 12; t++) {
        int col = h * HD + t*8 + c2_;
        *(uint32_t*)(aout + mrow0 + col) = pack_f16x2(o[t][0]*il0, o[t][1]*il0);
        *(uint32_t*)(aout + mrow1 + col) = pack_f16x2(o[t][2]*il1, o[t][3]*il1);
    }
}

// ---------------------------------------------------------------------------

extern "C" void kernel_launch(void* const* d_in, const int* in_sizes, int n_in,
                              void* d_out, int out_size)
{
    const float* hidden = (const float*)d_in[0];
    const float* w_qkv  = (const float*)d_in[2];
    const float* w_o    = (const float*)d_in[3];
    float* out = (float*)d_out;

    float *qkv;
    __half *h_f16, *wq_hi, *wq_lo, *wo_hi, *wo_lo, *a_f16;
    __half *q_hi, *q_lo, *k_f16, *v_hi, *v_lo;
    cudaGetSymbolAddress((void**)&qkv,   g_qkv);
    cudaGetSymbolAddress((void**)&h_f16, g_h_f16);
    cudaGetSymbolAddress((void**)&wq_hi, g_wq_hi);
    cudaGetSymbolAddress((void**)&wq_lo, g_wq_lo);
    cudaGetSymbolAddress((void**)&wo_hi, g_wo_hi);
    cudaGetSymbolAddress((void**)&wo_lo, g_wo_lo);
    cudaGetSymbolAddress((void**)&a_f16, g_a_f16);
    cudaGetSymbolAddress((void**)&q_hi,  g_q_hi);
    cudaGetSymbolAddress((void**)&q_lo,  g_q_lo);
    cudaGetSymbolAddress((void**)&k_f16, g_k_f16);
    cudaGetSymbolAddress((void**)&v_hi,  g_v_hi);
    cudaGetSymbolAddress((void**)&v_lo,  g_v_lo);

    cudaFuncSetAttribute(gemm_2xf16, cudaFuncAttributeMaxDynamicSharedMemorySize, GEMM_SMEM);
    cudaFuncSetAttribute(attn_mma,   cudaFuncAttributeMaxDynamicSharedMemorySize, ATT_SMEM);

    {
        int n4;
        n4 = (M_ * H_) / 4;
        round_f16<<<(n4 + 255)/256, 256>>>(hidden, h_f16, n4);
        n4 = (QKV_W * H_) / 4;
        split_f16<<<(n4 + 255)/256, 256>>>(w_qkv, wq_hi, wq_lo, n4);
        n4 = (H_ * H_) / 4;
        split_f16<<<(n4 + 255)/256, 256>>>(w_o, wo_hi, wo_lo, n4);
    }

    gemm_2xf16<<<dim3(QKV_W/128, M_/128), 256, GEMM_SMEM>>>(
        h_f16, wq_hi, wq_lo, qkv, QKV_W, H_);

    {
        int total = B_ * S_ * (NH + NKV) * (HD/2);
        rope_split<<<(total + 255)/256, 256>>>(qkv, q_hi, q_lo, k_f16);
        int vt = B_ * S_ * NKV * (HD/4);
        v_split<<<(vt + 255)/256, 256>>>(qkv, v_hi, v_lo);
    }

    attn_mma<<<dim3(S_/128, B_*NH), 256, ATT_SMEM>>>(
        q_hi, q_lo, k_f16, v_hi, v_lo, a_f16);

    gemm_2xf16<<<dim3(H_/128, M_/128), 256, GEMM_SMEM>>>(
        a_f16, wo_hi, wo_lo, out, H_, H_);
}

// round 11
// speedup vs baseline: 2.2581x; 1.4729x over previous
#include <cuda_runtime.h>
#include <cuda_bf16.h>
#include <cuda_fp16.h>
#include <math.h>
#include <stdint.h>

#define B_   2
#define S_   2048
#define H_   3072
#define NH   32
#define NKV  8
#define HD   96
#define QKV_W (NH*HD + 2*NKV*HD)   // 4608
#define M_   (B_*S_)               // 4096

// ---------------- scratch (device globals: allocation-free rule) -----------
__device__ float g_qkv[(size_t)M_ * QKV_W];
__device__ __half g_h_f16[(size_t)M_ * H_];
__device__ __half g_wq_f16[(size_t)QKV_W * H_];
__device__ __half g_wo_f16[(size_t)H_ * H_];
__device__ __half g_a_f16[(size_t)M_ * H_];
__device__ __half g_q_hi[(size_t)B_*NH*S_*HD],  g_q_lo[(size_t)B_*NH*S_*HD];
__device__ __half g_k_f16[(size_t)B_*NKV*S_*HD];
__device__ __half g_v_hi[(size_t)B_*NKV*S_*HD], g_v_lo[(size_t)B_*NKV*S_*HD];

// ---------------- base-target PTX helpers ----------------------------------
__device__ __forceinline__ void cp_async16(uint32_t dst, const void* src) {
    asm volatile("cp.async.cg.shared.global [%0], [%1], 16;"
                 :: "r"(dst), "l"(src) : "memory");
}
#define CP_COMMIT() asm volatile("cp.async.commit_group;" ::: "memory")
#define CP_WAIT(n)  asm volatile("cp.async.wait_group %0;" :: "n"(n) : "memory")

__device__ __forceinline__ void ldsm4(uint32_t& r0, uint32_t& r1, uint32_t& r2,
                                      uint32_t& r3, uint32_t addr) {
    asm volatile("ldmatrix.sync.aligned.m8n8.x4.shared.b16 {%0,%1,%2,%3}, [%4];"
                 : "=r"(r0), "=r"(r1), "=r"(r2), "=r"(r3) : "r"(addr));
}
__device__ __forceinline__ void ldsm4t(uint32_t& r0, uint32_t& r1, uint32_t& r2,
                                       uint32_t& r3, uint32_t addr) {
    asm volatile("ldmatrix.sync.aligned.m8n8.x4.trans.shared.b16 {%0,%1,%2,%3}, [%4];"
                 : "=r"(r0), "=r"(r1), "=r"(r2), "=r"(r3) : "r"(addr));
}
// fp16 mma
__device__ __forceinline__ void mma16816h(float* c, uint32_t a0, uint32_t a1,
                                          uint32_t a2, uint32_t a3,
                                          uint32_t b0, uint32_t b1) {
    asm volatile(
        "mma.sync.aligned.m16n8k16.row.col.f32.f16.f16.f32 "
        "{%0,%1,%2,%3}, {%4,%5,%6,%7}, {%8,%9}, {%0,%1,%2,%3};"
        : "+f"(c[0]), "+f"(c[1]), "+f"(c[2]), "+f"(c[3])
        : "r"(a0), "r"(a1), "r"(a2), "r"(a3), "r"(b0), "r"(b1));
}

__device__ __forceinline__ uint32_t pack_f16x2(float lo, float hi) {
    __half2 p = __floats2half2_rn(lo, hi);
    return *(uint32_t*)&p;
}

// ---------------------------------------------------------------------------
// fp32 -> fp16 round
// ---------------------------------------------------------------------------
__global__ void round_f16(const float* __restrict__ x, __half* __restrict__ h, int n4)
{
    int i = blockIdx.x * blockDim.x + threadIdx.x;
    if (i >= n4) return;
    float4 v = ((const float4*)x)[i];
    ((__half2*)h)[2*i]   = __floats2half2_rn(v.x, v.y);
    ((__half2*)h)[2*i+1] = __floats2half2_rn(v.z, v.w);
}

// ---------------------------------------------------------------------------
// 1-pass fp16 mma.sync GEMM (NT): C = A * B^T, both operands fp16-rounded.
// 128x128 CTA tile, BK=64, 2-stage, 2 CTAs/SM.
// ---------------------------------------------------------------------------
#define BK      64
#define LDS_    72
#define PLANE_B (128 * LDS_ * 2)      // 18432
#define BUF_B   (2 * PLANE_B)         // 36864  (A | B)
#define GEMM_SMEM (2 * BUF_B)         // 73728  (2 CTAs/SM)

__global__ __launch_bounds__(256, 2) void gemm_f16(
    const __half* __restrict__ A, const __half* __restrict__ Bw,
    float* __restrict__ C, int N, int K)
{
    extern __shared__ __align__(128) char smc[];
    const uint32_t sbase = (uint32_t)__cvta_generic_to_shared(smc);
    const int tid  = threadIdx.x;
    const int warp = tid >> 5, lane = tid & 31;
    const int bm = blockIdx.y * 128, bn = blockIdx.x * 128;
    const int wm = (warp >> 2) * 64;
    const int wn = (warp & 3) * 32;

    const __half* srcs[2] = { A + (size_t)bm * K, Bw + (size_t)bn * K };

    const int nch = K / BK;

    auto load_chunk = [&](int kc, int bb) {
        uint32_t sb = sbase + bb * BUF_B;
        #pragma unroll
        for (int p = 0; p < 2; p++) {
            const __half* sp = srcs[p] + kc * BK;
            uint32_t pb = sb + p * PLANE_B;
            #pragma unroll
            for (int t = 0; t < 4; t++) {
                int f = tid + t * 256;
                int r = f >> 3, j = f & 7;
                cp_async16(pb + r * (LDS_ * 2) + j * 16,
                           sp + (size_t)r * K + j * 8);
            }
        }
        CP_COMMIT();
    };

    float c[4][4][4];
    #pragma unroll
    for (int i = 0; i < 4; i++)
        #pragma unroll
        for (int j = 0; j < 4; j++)
            #pragma unroll
            for (int q = 0; q < 4; q++) c[i][j][q] = 0.f;

    load_chunk(0, 0);

    const int arow = lane & 15;
    const int ak8  = (lane >> 4) * 8;
    const int brow = (lane & 7) + ((lane >> 4) << 3);
    const int bk8  = ((lane >> 3) & 1) * 8;

    #pragma unroll 1
    for (int kc = 0; kc < nch; kc++) {
        const int bb = kc & 1;
        CP_WAIT(0);
        __syncthreads();
        if (kc + 1 < nch) load_chunk(kc + 1, bb ^ 1);

        const uint32_t sA = sbase + bb * BUF_B;
        const uint32_t sB = sA + PLANE_B;

        #pragma unroll
        for (int ks = 0; ks < 4; ks++) {
            const int k0 = ks * 16;
            uint32_t bh[4][2];
            #pragma unroll
            for (int tp = 0; tp < 2; tp++) {
                uint32_t off = (uint32_t)((wn + tp*16 + brow) * LDS_ + k0 + bk8) * 2;
                ldsm4(bh[tp*2][0], bh[tp*2][1], bh[tp*2+1][0], bh[tp*2+1][1], sB + off);
            }
            #pragma unroll
            for (int ti = 0; ti < 4; ti++) {
                uint32_t off = (uint32_t)((wm + ti*16 + arow) * LDS_ + k0 + ak8) * 2;
                uint32_t ah[4];
                ldsm4(ah[0], ah[1], ah[2], ah[3], sA + off);
                mma16816h(c[ti][0], ah[0], ah[1], ah[2], ah[3], bh[0][0], bh[0][1]);
                mma16816h(c[ti][1], ah[0], ah[1], ah[2], ah[3], bh[1][0], bh[1][1]);
                mma16816h(c[ti][2], ah[0], ah[1], ah[2], ah[3], bh[2][0], bh[2][1]);
                mma16816h(c[ti][3], ah[0], ah[1], ah[2], ah[3], bh[3][0], bh[3][1]);
            }
        }
    }

    const int cr = lane >> 2, cc = (lane & 3) * 2;
    #pragma unroll
    for (int ti = 0; ti < 4; ti++) {
        #pragma unroll
        for (int tj = 0; tj < 4; tj++) {
            int r0 = bm + wm + ti*16 + cr;
            int col = bn + wn + tj*8 + cc;
            *(float2*)(C + (size_t)r0 * N + col)       = make_float2(c[ti][tj][0], c[ti][tj][1]);
            *(float2*)(C + (size_t)(r0 + 8) * N + col) = make_float2(c[ti][tj][2], c[ti][tj][3]);
        }
    }
}

// ---------------------------------------------------------------------------
// RoPE: Q -> fp16 hi/lo planes (scale folded), K -> single fp16 plane.
// ---------------------------------------------------------------------------
__global__ void rope_split(const float* __restrict__ qkv,
                           __half* __restrict__ qhi, __half* __restrict__ qlo,
                           __half* __restrict__ kf)
{
    const int total = B_ * S_ * (NH + NKV) * (HD / 2);
    int i = blockIdx.x * blockDim.x + threadIdx.x;
    if (i >= total) return;
    int d    = i % (HD/2);
    int t    = i / (HD/2);
    int head = t % (NH + NKV);
    int bs   = t / (NH + NKV);
    int b    = bs / S_;
    int s    = bs % S_;

    float inv = expf(-(float)d * (logf(10000.0f) / 48.0f));
    float ang = (float)s * inv;
    float sn, cs;
    sincosf(ang, &sn, &cs);

    const float* base = qkv + (size_t)bs * QKV_W + head * HD;
    float x1 = base[d];
    float x2 = base[d + 48];
    float y1 = x1 * cs - x2 * sn;
    float y2 = x2 * cs + x1 * sn;

    if (head < NH) {
        const float scale = 0.10206207261596577f;
        y1 *= scale; y2 *= scale;
        size_t idx = ((size_t)(b * NH + head) * S_ + s) * HD;
        float h1 = __half2float(__float2half_rn(y1));
        float h2 = __half2float(__float2half_rn(y2));
        qhi[idx + d]      = __float2half_rn(h1);
        qhi[idx + d + 48] = __float2half_rn(h2);
        qlo[idx + d]      = __float2half_rn(y1 - h1);
        qlo[idx + d + 48] = __float2half_rn(y2 - h2);
    } else {
        size_t idx = ((size_t)(b * NKV + (head - NH)) * S_ + s) * HD;
        kf[idx + d]      = __float2half_rn(y1);
        kf[idx + d + 48] = __float2half_rn(y2);
    }
}

__global__ void v_split(const float* __restrict__ qkv,
                        __half* __restrict__ vhi, __half* __restrict__ vlo)
{
    const int total = B_ * S_ * NKV * (HD / 4);
    int i = blockIdx.x * blockDim.x + threadIdx.x;
    if (i >= total) return;
    int d4  = i % (HD/4);
    int t   = i / (HD/4);
    int kvh = t % NKV;
    int bs  = t / NKV;
    int b   = bs / S_;
    int s   = bs % S_;

    const float* src = qkv + (size_t)bs * QKV_W + NH*HD + NKV*HD + kvh*HD + d4*4;
    float4 v = *(const float4*)src;
    size_t idx = ((size_t)(b * NKV + kvh) * S_ + s) * HD + d4*4;
    float h0 = __half2float(__float2half_rn(v.x));
    float h1 = __half2float(__float2half_rn(v.y));
    float h2 = __half2float(__float2half_rn(v.z));
    float h3 = __half2float(__float2half_rn(v.w));
    *(__half2*)(vhi + idx)     = __floats2half2_rn(h0, h1);
    *(__half2*)(vhi + idx + 2) = __floats2half2_rn(h2, h3);
    *(__half2*)(vlo + idx)     = __floats2half2_rn(v.x - h0, v.y - h1);
    *(__half2*)(vlo + idx + 2) = __floats2half2_rn(v.z - h2, v.w - h3);
}

// ---------------------------------------------------------------------------
// Flash attention, 2-pass fp16 mma. CTA: 128 queries x one (b,h).
// QK: (Qhi+Qlo) x Kf16. PV: Pf16 x (Vhi+Vlo). 8 warps x 16 rows,
// 64-key tiles, 3-stage KV ring.
// ---------------------------------------------------------------------------
#define ALDS   104
#define QBYTES (128 * ALDS * 2)         // 26624
#define KVTILE (64 * ALDS * 2)          // 13312
#define KVBUF  (3 * KVTILE)             // 39936
#define ASTAGES 3
#define ATT_SMEM (2*QBYTES + ASTAGES*KVBUF)   // 173056

__global__ __launch_bounds__(256, 1) void attn_mma(
    const __half* __restrict__ qhi, const __half* __restrict__ qlo,
    const __half* __restrict__ kf,
    const __half* __restrict__ vhi, const __half* __restrict__ vlo,
    __half* __restrict__ aout)
{
    extern __shared__ __align__(128) char smc[];
    const uint32_t sb  = (uint32_t)__cvta_generic_to_shared(smc);
    const uint32_t sQh = sb, sQl = sb + QBYTES;
    const uint32_t sKV = sb + 2 * QBYTES;

    const int tid  = threadIdx.x;
    const int warp = tid >> 5, lane = tid & 31;
    const int qt = blockIdx.x;
    const int bh = blockIdx.y;
    const int b  = bh >> 5, h = bh & 31, kvh = h >> 2;
    const int q0 = qt * 128;
    const int wm = warp * 16;

    const __half* qsh = qhi + ((size_t)(b*NH + h) * S_ + q0) * HD;
    const __half* qsl = qlo + ((size_t)(b*NH + h) * S_ + q0) * HD;
    const __half* ksf = kf  + (size_t)(b*NKV + kvh) * S_ * HD;
    const __half* vsh = vhi + (size_t)(b*NKV + kvh) * S_ * HD;
    const __half* vsl = vlo + (size_t)(b*NKV + kvh) * S_ * HD;

    #pragma unroll
    for (int u = 0; u < 6; u++) {
        int f = tid + u * 256;
        int r = f / 12, cidx = f % 12;
        cp_async16(sQh + r * (ALDS*2) + cidx * 16, qsh + (size_t)r * HD + cidx * 8);
        cp_async16(sQl + r * (ALDS*2) + cidx * 16, qsl + (size_t)r * HD + cidx * 8);
    }

    auto load_kv = [&](int kt, int bb) {
        uint32_t base = sKV + bb * KVBUF;
        int k0 = kt * 64;
        #pragma unroll
        for (int u = 0; u < 3; u++) {
            int f = tid + u * 256;
            int r = f / 12, cidx = f % 12;
            size_t g = (size_t)(k0 + r) * HD + cidx * 8;
            uint32_t o = r * (ALDS*2) + cidx * 16;
            cp_async16(base + 0*KVTILE + o, ksf + g);
            cp_async16(base + 1*KVTILE + o, vsh + g);
            cp_async16(base + 2*KVTILE + o, vsl + g);
        }
        CP_COMMIT();
    };

    const int nkt = 2 * qt + 2;
    load_kv(0, 0);
    if (nkt > 1) load_kv(1, 1); else CP_COMMIT();

    const int arow = lane & 15;
    const int ak8  = (lane >> 4) * 8;
    const int brow = (lane & 7) + ((lane >> 4) << 3);
    const int bk8  = ((lane >> 3) & 1) * 8;
    const int vrow = lane & 15;
    const int vn8  = (lane >> 4) * 8;
    const int r_   = lane >> 2;
    const int c2_  = (lane & 3) * 2;

    float o[12][4];
    #pragma unroll
    for (int t = 0; t < 12; t++)
        #pragma unroll
        for (int q = 0; q < 4; q++) o[t][q] = 0.f;
    float m0 = -1e30f, m1 = -1e30f, l0 = 0.f, l1 = 0.f;

    const int row_g0 = q0 + wm + r_;
    const int wmax   = q0 + wm + 15;

    int bb = 0;
    #pragma unroll 1
    for (int kt = 0; kt < nkt; kt++) {
        const int k0 = kt * 64;
        CP_WAIT(1);
        __syncthreads();
        if (kt + 2 < nkt) {
            int nb = bb + 2; if (nb >= ASTAGES) nb -= ASTAGES;
            load_kv(kt + 2, nb);
        } else CP_COMMIT();

        if (k0 <= wmax) {
            const uint32_t sK  = sKV + bb * KVBUF;
            const uint32_t sVh = sK + KVTILE;
            const uint32_t sVl = sK + 2 * KVTILE;

            float s[8][4];
            #pragma unroll
            for (int t = 0; t < 8; t++)
                #pragma unroll
                for (int q = 0; q < 4; q++) s[t][q] = 0.f;

            #pragma unroll
            for (int ks = 0; ks < 6; ks++) {
                uint32_t aoff = (uint32_t)((wm + arow) * ALDS + ks*16 + ak8) * 2;
                uint32_t ah[4], al[4];
                ldsm4(ah[0], ah[1], ah[2], ah[3], sQh + aoff);
                ldsm4(al[0], al[1], al[2], al[3], sQl + aoff);
                uint32_t kh_[4][4];
                #pragma unroll
                for (int np = 0; np < 4; np++) {
                    uint32_t boff = (uint32_t)((np*16 + brow) * ALDS + ks*16 + bk8) * 2;
                    ldsm4(kh_[np][0], kh_[np][1], kh_[np][2], kh_[np][3], sK + boff);
                }
                #pragma unroll
                for (int np = 0; np < 4; np++) {
                    mma16816h(s[2*np],   ah[0],ah[1],ah[2],ah[3], kh_[np][0], kh_[np][1]);
                    mma16816h(s[2*np+1], ah[0],ah[1],ah[2],ah[3], kh_[np][2], kh_[np][3]);
                }
                #pragma unroll
                for (int np = 0; np < 4; np++) {
                    mma16816h(s[2*np],   al[0],al[1],al[2],al[3], kh_[np][0], kh_[np][1]);
                    mma16816h(s[2*np+1], al[0],al[1],al[2],al[3], kh_[np][2], kh_[np][3]);
                }
            }

            if (k0 + 63 > q0 + wm) {
                #pragma unroll
                for (int t = 0; t < 8; t++) {
                    int col = k0 + t*8 + c2_;
                    if (col     > row_g0)     s[t][0] = -1e30f;
                    if (col + 1 > row_g0)     s[t][1] = -1e30f;
                    if (col     > row_g0 + 8) s[t][2] = -1e30f;
                    if (col + 1 > row_g0 + 8) s[t][3] = -1e30f;
                }
            }

            float mx0 = -1e30f, mx1 = -1e30f;
            #pragma unroll
            for (int t = 0; t < 8; t++) {
                mx0 = fmaxf(mx0, fmaxf(s[t][0], s[t][1]));
                mx1 = fmaxf(mx1, fmaxf(s[t][2], s[t][3]));
            }
            mx0 = fmaxf(mx0, __shfl_xor_sync(0xffffffff, mx0, 1));
            mx0 = fmaxf(mx0, __shfl_xor_sync(0xffffffff, mx0, 2));
            mx1 = fmaxf(mx1, __shfl_xor_sync(0xffffffff, mx1, 1));
            mx1 = fmaxf(mx1, __shfl_xor_sync(0xffffffff, mx1, 2));

            float mn0 = fmaxf(m0, mx0), mn1 = fmaxf(m1, mx1);
            float al0 = __expf(m0 - mn0), al1 = __expf(m1 - mn1);
            m0 = mn0; m1 = mn1;

            float sum0 = 0.f, sum1 = 0.f;
            #pragma unroll
            for (int t = 0; t < 8; t++) {
                s[t][0] = __expf(s[t][0] - m0);
                s[t][1] = __expf(s[t][1] - m0);
                s[t][2] = __expf(s[t][2] - m1);
                s[t][3] = __expf(s[t][3] - m1);
                sum0 += s[t][0] + s[t][1];
                sum1 += s[t][2] + s[t][3];
            }
            sum0 += __shfl_xor_sync(0xffffffff, sum0, 1);
            sum0 += __shfl_xor_sync(0xffffffff, sum0, 2);
            sum1 += __shfl_xor_sync(0xffffffff, sum1, 1);
            sum1 += __shfl_xor_sync(0xffffffff, sum1, 2);
            l0 = l0 * al0 + sum0;
            l1 = l1 * al1 + sum1;

            #pragma unroll
            for (int t = 0; t < 12; t++) {
                o[t][0] *= al0; o[t][1] *= al0;
                o[t][2] *= al1; o[t][3] *= al1;
            }

            #pragma unroll
            for (int ks = 0; ks < 4; ks++) {
                const int j0 = 2*ks, j1 = 2*ks + 1;
                uint32_t ph[4];
                ph[0] = pack_f16x2(s[j0][0], s[j0][1]);
                ph[1] = pack_f16x2(s[j0][2], s[j0][3]);
                ph[2] = pack_f16x2(s[j1][0], s[j1][1]);
                ph[3] = pack_f16x2(s[j1][2], s[j1][3]);
                #pragma unroll
                for (int npp = 0; npp < 3; npp++) {
                    const int np = 2 * npp;
                    uint32_t voffa = (uint32_t)((ks*16 + vrow) * ALDS + np*16 + vn8) * 2;
                    uint32_t voffb = (uint32_t)((ks*16 + vrow) * ALDS + (np+1)*16 + vn8) * 2;
                    uint32_t vha[4], vhb[4], vla[4], vlb[4];
                    ldsm4t(vha[0], vha[1], vha[2], vha[3], sVh + voffa);
                    ldsm4t(vhb[0], vhb[1], vhb[2], vhb[3], sVh + voffb);
                    ldsm4t(vla[0], vla[1], vla[2], vla[3], sVl + voffa);
                    ldsm4t(vlb[0], vlb[1], vlb[2], vlb[3], sVl + voffb);
                    mma16816h(o[2*np],   ph[0],ph[1],ph[2],ph[3], vha[0], vha[1]);
                    mma16816h(o[2*np+1], ph[0],ph[1],ph[2],ph[3], vha[2], vha[3]);
                    mma16816h(o[2*np+2], ph[0],ph[1],ph[2],ph[3], vhb[0], vhb[1]);
                    mma16816h(o[2*np+3], ph[0],ph[1],ph[2],ph[3], vhb[2], vhb[3]);
                    mma16816h(o[2*np],   ph[0],ph[1],ph[2],ph[3], vla[0], vla[1]);
                    mma16816h(o[2*np+1], ph[0],ph[1],ph[2],ph[3], vla[2], vla[3]);
                    mma16816h(o[2*np+2], ph[0],ph[1],ph[2],ph[3], vlb[0], vlb[1]);
                    mma16816h(o[2*np+3], ph[0],ph[1],ph[2],ph[3], vlb[2], vlb[3]);
                }
            }
        }
        if (++bb == ASTAGES) bb = 0;
    }

    const float il0 = 1.f / l0, il1 = 1.f / l1;
    const size_t mrow0 = (size_t)(b * S_ + row_g0) * H_;
    const size_t mrow1 = mrow0 + 8 * (size_t)H_;
    #pragma unroll
    for (int t = 0; t < 12; t++) {
        int col = h * HD + t*8 + c2_;
        *(uint32_t*)(aout + mrow0 + col) = pack_f16x2(o[t][0]*il0, o[t][1]*il0);
        *(uint32_t*)(aout + mrow1 + col) = pack_f16x2(o[t][2]*il1, o[t][3]*il1);
    }
}

// ---------------------------------------------------------------------------

extern "C" void kernel_launch(void* const* d_in, const int* in_sizes, int n_in,
                              void* d_out, int out_size)
{
    const float* hidden = (const float*)d_in[0];
    const float* w_qkv  = (const float*)d_in[2];
    const float* w_o    = (const float*)d_in[3];
    float* out = (float*)d_out;

    float *qkv;
    __half *h_f16, *wq_f16, *wo_f16, *a_f16;
    __half *q_hi, *q_lo, *k_f16, *v_hi, *v_lo;
    cudaGetSymbolAddress((void**)&qkv,    g_qkv);
    cudaGetSymbolAddress((void**)&h_f16,  g_h_f16);
    cudaGetSymbolAddress((void**)&wq_f16, g_wq_f16);
    cudaGetSymbolAddress((void**)&wo_f16, g_wo_f16);
    cudaGetSymbolAddress((void**)&a_f16,  g_a_f16);
    cudaGetSymbolAddress((void**)&q_hi,   g_q_hi);
    cudaGetSymbolAddress((void**)&q_lo,   g_q_lo);
    cudaGetSymbolAddress((void**)&k_f16,  g_k_f16);
    cudaGetSymbolAddress((void**)&v_hi,   g_v_hi);
    cudaGetSymbolAddress((void**)&v_lo,   g_v_lo);

    cudaFuncSetAttribute(gemm_f16, cudaFuncAttributeMaxDynamicSharedMemorySize, GEMM_SMEM);
    cudaFuncSetAttribute(attn_mma, cudaFuncAttributeMaxDynamicSharedMemorySize, ATT_SMEM);

    // 1) round activations + weights to fp16
    {
        int n4;
        n4 = (M_ * H_) / 4;
        round_f16<<<(n4 + 255)/256, 256>>>(hidden, h_f16, n4);
        n4 = (QKV_W * H_) / 4;
        round_f16<<<(n4 + 255)/256, 256>>>(w_qkv, wq_f16, n4);
        n4 = (H_ * H_) / 4;
        round_f16<<<(n4 + 255)/256, 256>>>(w_o, wo_f16, n4);
    }

    // 2) QKV projection (1-pass fp16 HMMA)
    gemm_f16<<<dim3(QKV_W/128, M_/128), 256, GEMM_SMEM>>>(
        h_f16, wq_f16, qkv, QKV_W, H_);

    // 3) RoPE + splits (attention operands)
    {
        int total = B_ * S_ * (NH + NKV) * (HD/2);
        rope_split<<<(total + 255)/256, 256>>>(qkv, q_hi, q_lo, k_f16);
        int vt = B_ * S_ * NKV * (HD/4);
        v_split<<<(vt + 255)/256, 256>>>(qkv, v_hi, v_lo);
    }

    // 4) causal GQA flash attention (2-pass fp16)
    attn_mma<<<dim3(S_/128, B_*NH), 256, ATT_SMEM>>>(
        q_hi, q_lo, k_f16, v_hi, v_lo, a_f16);

    // 5) output projection (1-pass fp16 HMMA)
    gemm_f16<<<dim3(H_/128, M_/128), 256, GEMM_SMEM>>>(
        a_f16, wo_f16, out, H_, H_);
}

// round 12
// speedup vs baseline: 2.6036x; 1.1530x over previous
#include <cuda_runtime.h>
#include <cuda_bf16.h>
#include <cuda_fp16.h>
#include <math.h>
#include <stdint.h>

#define B_   2
#define S_   2048
#define H_   3072
#define NH   32
#define NKV  8
#define HD   96
#define QKV_W (NH*HD + 2*NKV*HD)   // 4608
#define M_   (B_*S_)               // 4096

// ---------------- scratch (device globals: allocation-free rule) -----------
__device__ float g_qkv[(size_t)M_ * QKV_W];
__device__ __half g_h_f16[(size_t)M_ * H_];
__device__ __half g_wq_f16[(size_t)QKV_W * H_];
__device__ __half g_wo_f16[(size_t)H_ * H_];
__device__ __half g_a_f16[(size_t)M_ * H_];
__device__ __half g_q_f16[(size_t)B_*NH*S_*HD];
__device__ __half g_k_f16[(size_t)B_*NKV*S_*HD];
__device__ __half g_v_f16[(size_t)B_*NKV*S_*HD];

// ---------------- base-target PTX helpers ----------------------------------
__device__ __forceinline__ void cp_async16(uint32_t dst, const void* src) {
    asm volatile("cp.async.cg.shared.global [%0], [%1], 16;"
                 :: "r"(dst), "l"(src) : "memory");
}
#define CP_COMMIT() asm volatile("cp.async.commit_group;" ::: "memory")
#define CP_WAIT(n)  asm volatile("cp.async.wait_group %0;" :: "n"(n) : "memory")

__device__ __forceinline__ void ldsm4(uint32_t& r0, uint32_t& r1, uint32_t& r2,
                                      uint32_t& r3, uint32_t addr) {
    asm volatile("ldmatrix.sync.aligned.m8n8.x4.shared.b16 {%0,%1,%2,%3}, [%4];"
                 : "=r"(r0), "=r"(r1), "=r"(r2), "=r"(r3) : "r"(addr));
}
__device__ __forceinline__ void ldsm4t(uint32_t& r0, uint32_t& r1, uint32_t& r2,
                                       uint32_t& r3, uint32_t addr) {
    asm volatile("ldmatrix.sync.aligned.m8n8.x4.trans.shared.b16 {%0,%1,%2,%3}, [%4];"
                 : "=r"(r0), "=r"(r1), "=r"(r2), "=r"(r3) : "r"(addr));
}
__device__ __forceinline__ void mma16816h(float* c, uint32_t a0, uint32_t a1,
                                          uint32_t a2, uint32_t a3,
                                          uint32_t b0, uint32_t b1) {
    asm volatile(
        "mma.sync.aligned.m16n8k16.row.col.f32.f16.f16.f32 "
        "{%0,%1,%2,%3}, {%4,%5,%6,%7}, {%8,%9}, {%0,%1,%2,%3};"
        : "+f"(c[0]), "+f"(c[1]), "+f"(c[2]), "+f"(c[3])
        : "r"(a0), "r"(a1), "r"(a2), "r"(a3), "r"(b0), "r"(b1));
}

__device__ __forceinline__ uint32_t pack_f16x2(float lo, float hi) {
    __half2 p = __floats2half2_rn(lo, hi);
    return *(uint32_t*)&p;
}

// ---------------------------------------------------------------------------
// fp32 -> fp16 round
// ---------------------------------------------------------------------------
__global__ void round_f16(const float* __restrict__ x, __half* __restrict__ h, int n4)
{
    int i = blockIdx.x * blockDim.x + threadIdx.x;
    if (i >= n4) return;
    float4 v = ((const float4*)x)[i];
    ((__half2*)h)[2*i]   = __floats2half2_rn(v.x, v.y);
    ((__half2*)h)[2*i+1] = __floats2half2_rn(v.z, v.w);
}

// ---------------------------------------------------------------------------
// 1-pass fp16 mma.sync GEMM (NT). 128x128 CTA tile, BK=64, 2-stage, 2 CTAs/SM.
// ---------------------------------------------------------------------------
#define BK      64
#define LDS_    72
#define PLANE_B (128 * LDS_ * 2)      // 18432
#define BUF_B   (2 * PLANE_B)         // 36864
#define GEMM_SMEM (2 * BUF_B)         // 73728

__global__ __launch_bounds__(256, 2) void gemm_f16(
    const __half* __restrict__ A, const __half* __restrict__ Bw,
    float* __restrict__ C, int N, int K)
{
    extern __shared__ __align__(128) char smc[];
    const uint32_t sbase = (uint32_t)__cvta_generic_to_shared(smc);
    const int tid  = threadIdx.x;
    const int warp = tid >> 5, lane = tid & 31;
    const int bm = blockIdx.y * 128, bn = blockIdx.x * 128;
    const int wm = (warp >> 2) * 64;
    const int wn = (warp & 3) * 32;

    const __half* srcs[2] = { A + (size_t)bm * K, Bw + (size_t)bn * K };

    const int nch = K / BK;

    auto load_chunk = [&](int kc, int bb) {
        uint32_t sb = sbase + bb * BUF_B;
        #pragma unroll
        for (int p = 0; p < 2; p++) {
            const __half* sp = srcs[p] + kc * BK;
            uint32_t pb = sb + p * PLANE_B;
            #pragma unroll
            for (int t = 0; t < 4; t++) {
                int f = tid + t * 256;
                int r = f >> 3, j = f & 7;
                cp_async16(pb + r * (LDS_ * 2) + j * 16,
                           sp + (size_t)r * K + j * 8);
            }
        }
        CP_COMMIT();
    };

    float c[4][4][4];
    #pragma unroll
    for (int i = 0; i < 4; i++)
        #pragma unroll
        for (int j = 0; j < 4; j++)
            #pragma unroll
            for (int q = 0; q < 4; q++) c[i][j][q] = 0.f;

    load_chunk(0, 0);

    const int arow = lane & 15;
    const int ak8  = (lane >> 4) * 8;
    const int brow = (lane & 7) + ((lane >> 4) << 3);
    const int bk8  = ((lane >> 3) & 1) * 8;

    #pragma unroll 1
    for (int kc = 0; kc < nch; kc++) {
        const int bb = kc & 1;
        CP_WAIT(0);
        __syncthreads();
        if (kc + 1 < nch) load_chunk(kc + 1, bb ^ 1);

        const uint32_t sA = sbase + bb * BUF_B;
        const uint32_t sB = sA + PLANE_B;

        #pragma unroll
        for (int ks = 0; ks < 4; ks++) {
            const int k0 = ks * 16;
            uint32_t bh[4][2];
            #pragma unroll
            for (int tp = 0; tp < 2; tp++) {
                uint32_t off = (uint32_t)((wn + tp*16 + brow) * LDS_ + k0 + bk8) * 2;
                ldsm4(bh[tp*2][0], bh[tp*2][1], bh[tp*2+1][0], bh[tp*2+1][1], sB + off);
            }
            #pragma unroll
            for (int ti = 0; ti < 4; ti++) {
                uint32_t off = (uint32_t)((wm + ti*16 + arow) * LDS_ + k0 + ak8) * 2;
                uint32_t ah[4];
                ldsm4(ah[0], ah[1], ah[2], ah[3], sA + off);
                mma16816h(c[ti][0], ah[0], ah[1], ah[2], ah[3], bh[0][0], bh[0][1]);
                mma16816h(c[ti][1], ah[0], ah[1], ah[2], ah[3], bh[1][0], bh[1][1]);
                mma16816h(c[ti][2], ah[0], ah[1], ah[2], ah[3], bh[2][0], bh[2][1]);
                mma16816h(c[ti][3], ah[0], ah[1], ah[2], ah[3], bh[3][0], bh[3][1]);
            }
        }
    }

    const int cr = lane >> 2, cc = (lane & 3) * 2;
    #pragma unroll
    for (int ti = 0; ti < 4; ti++) {
        #pragma unroll
        for (int tj = 0; tj < 4; tj++) {
            int r0 = bm + wm + ti*16 + cr;
            int col = bn + wn + tj*8 + cc;
            *(float2*)(C + (size_t)r0 * N + col)       = make_float2(c[ti][tj][0], c[ti][tj][1]);
            *(float2*)(C + (size_t)(r0 + 8) * N + col) = make_float2(c[ti][tj][2], c[ti][tj][3]);
        }
    }
}

// ---------------------------------------------------------------------------
// RoPE: Q -> fp16 plane (scale folded), K -> fp16 plane.
// ---------------------------------------------------------------------------
__global__ void rope_split(const float* __restrict__ qkv,
                           __half* __restrict__ qf, __half* __restrict__ kf)
{
    const int total = B_ * S_ * (NH + NKV) * (HD / 2);
    int i = blockIdx.x * blockDim.x + threadIdx.x;
    if (i >= total) return;
    int d    = i % (HD/2);
    int t    = i / (HD/2);
    int head = t % (NH + NKV);
    int bs   = t / (NH + NKV);
    int b    = bs / S_;
    int s    = bs % S_;

    float inv = expf(-(float)d * (logf(10000.0f) / 48.0f));
    float ang = (float)s * inv;
    float sn, cs;
    sincosf(ang, &sn, &cs);

    const float* base = qkv + (size_t)bs * QKV_W + head * HD;
    float x1 = base[d];
    float x2 = base[d + 48];
    float y1 = x1 * cs - x2 * sn;
    float y2 = x2 * cs + x1 * sn;

    if (head < NH) {
        const float scale = 0.10206207261596577f;
        y1 *= scale; y2 *= scale;
        size_t idx = ((size_t)(b * NH + head) * S_ + s) * HD;
        qf[idx + d]      = __float2half_rn(y1);
        qf[idx + d + 48] = __float2half_rn(y2);
    } else {
        size_t idx = ((size_t)(b * NKV + (head - NH)) * S_ + s) * HD;
        kf[idx + d]      = __float2half_rn(y1);
        kf[idx + d + 48] = __float2half_rn(y2);
    }
}

// V: round to head-major fp16 plane.
__global__ void v_round(const float* __restrict__ qkv, __half* __restrict__ vf)
{
    const int total = B_ * S_ * NKV * (HD / 4);
    int i = blockIdx.x * blockDim.x + threadIdx.x;
    if (i >= total) return;
    int d4  = i % (HD/4);
    int t   = i / (HD/4);
    int kvh = t % NKV;
    int bs  = t / NKV;
    int b   = bs / S_;
    int s   = bs % S_;

    const float* src = qkv + (size_t)bs * QKV_W + NH*HD + NKV*HD + kvh*HD + d4*4;
    float4 v = *(const float4*)src;
    size_t idx = ((size_t)(b * NKV + kvh) * S_ + s) * HD + d4*4;
    *(__half2*)(vf + idx)     = __floats2half2_rn(v.x, v.y);
    *(__half2*)(vf + idx + 2) = __floats2half2_rn(v.z, v.w);
}

// ---------------------------------------------------------------------------
// Flash attention, 1-pass fp16 mma. CTA: 128 queries x one (b,h).
// 8 warps x 16 rows, 64-key tiles, 3-stage 2-plane KV ring, 2 CTAs/SM.
// ---------------------------------------------------------------------------
#define ALDS   104
#define QBYTES (128 * ALDS * 2)         // 26624
#define KVTILE (64 * ALDS * 2)          // 13312
#define KVBUF  (2 * KVTILE)             // 26624
#define ASTAGES 3
#define ATT_SMEM (QBYTES + ASTAGES*KVBUF)   // 106496 -> 2 CTAs/SM

__global__ __launch_bounds__(256, 2) void attn_mma(
    const __half* __restrict__ qf, const __half* __restrict__ kf,
    const __half* __restrict__ vf, __half* __restrict__ aout)
{
    extern __shared__ __align__(128) char smc[];
    const uint32_t sb  = (uint32_t)__cvta_generic_to_shared(smc);
    const uint32_t sQ  = sb;
    const uint32_t sKV = sb + QBYTES;

    const int tid  = threadIdx.x;
    const int warp = tid >> 5, lane = tid & 31;
    const int qt = blockIdx.x;
    const int bh = blockIdx.y;
    const int b  = bh >> 5, h = bh & 31, kvh = h >> 2;
    const int q0 = qt * 128;
    const int wm = warp * 16;

    const __half* qsf = qf + ((size_t)(b*NH + h) * S_ + q0) * HD;
    const __half* ksf = kf + (size_t)(b*NKV + kvh) * S_ * HD;
    const __half* vsf = vf + (size_t)(b*NKV + kvh) * S_ * HD;

    // Q tile: 128 rows x 12 16B chunks
    #pragma unroll
    for (int u = 0; u < 6; u++) {
        int f = tid + u * 256;            // 0..1535
        int r = f / 12, cidx = f % 12;
        cp_async16(sQ + r * (ALDS*2) + cidx * 16, qsf + (size_t)r * HD + cidx * 8);
    }

    auto load_kv = [&](int kt, int bb) {
        uint32_t base = sKV + bb * KVBUF;
        int k0 = kt * 64;
        #pragma unroll
        for (int u = 0; u < 3; u++) {
            int f = tid + u * 256;
            int r = f / 12, cidx = f % 12;
            size_t g = (size_t)(k0 + r) * HD + cidx * 8;
            uint32_t o = r * (ALDS*2) + cidx * 16;
            cp_async16(base + 0*KVTILE + o, ksf + g);
            cp_async16(base + 1*KVTILE + o, vsf + g);
        }
        CP_COMMIT();
    };

    const int nkt = 2 * qt + 2;
    load_kv(0, 0);
    if (nkt > 1) load_kv(1, 1); else CP_COMMIT();

    const int arow = lane & 15;
    const int ak8  = (lane >> 4) * 8;
    const int brow = (lane & 7) + ((lane >> 4) << 3);
    const int bk8  = ((lane >> 3) & 1) * 8;
    const int vrow = lane & 15;
    const int vn8  = (lane >> 4) * 8;
    const int r_   = lane >> 2;
    const int c2_  = (lane & 3) * 2;

    float o[12][4];
    #pragma unroll
    for (int t = 0; t < 12; t++)
        #pragma unroll
        for (int q = 0; q < 4; q++) o[t][q] = 0.f;
    float m0 = -1e30f, m1 = -1e30f, l0 = 0.f, l1 = 0.f;

    const int row_g0 = q0 + wm + r_;
    const int wmax   = q0 + wm + 15;

    int bb = 0;
    #pragma unroll 1
    for (int kt = 0; kt < nkt; kt++) {
        const int k0 = kt * 64;
        CP_WAIT(1);
        __syncthreads();
        if (kt + 2 < nkt) {
            int nb = bb + 2; if (nb >= ASTAGES) nb -= ASTAGES;
            load_kv(kt + 2, nb);
        } else CP_COMMIT();

        if (k0 <= wmax) {
            const uint32_t sK = sKV + bb * KVBUF;
            const uint32_t sV = sK + KVTILE;

            float s[8][4];
            #pragma unroll
            for (int t = 0; t < 8; t++)
                #pragma unroll
                for (int q = 0; q < 4; q++) s[t][q] = 0.f;

            #pragma unroll
            for (int ks = 0; ks < 6; ks++) {
                uint32_t aoff = (uint32_t)((wm + arow) * ALDS + ks*16 + ak8) * 2;
                uint32_t ah[4];
                ldsm4(ah[0], ah[1], ah[2], ah[3], sQ + aoff);
                #pragma unroll
                for (int np = 0; np < 4; np++) {
                    uint32_t boff = (uint32_t)((np*16 + brow) * ALDS + ks*16 + bk8) * 2;
                    uint32_t kh_[4];
                    ldsm4(kh_[0], kh_[1], kh_[2], kh_[3], sK + boff);
                    mma16816h(s[2*np],   ah[0],ah[1],ah[2],ah[3], kh_[0], kh_[1]);
                    mma16816h(s[2*np+1], ah[0],ah[1],ah[2],ah[3], kh_[2], kh_[3]);
                }
            }

            if (k0 + 63 > q0 + wm) {
                #pragma unroll
                for (int t = 0; t < 8; t++) {
                    int col = k0 + t*8 + c2_;
                    if (col     > row_g0)     s[t][0] = -1e30f;
                    if (col + 1 > row_g0)     s[t][1] = -1e30f;
                    if (col     > row_g0 + 8) s[t][2] = -1e30f;
                    if (col + 1 > row_g0 + 8) s[t][3] = -1e30f;
                }
            }

            float mx0 = -1e30f, mx1 = -1e30f;
            #pragma unroll
            for (int t = 0; t < 8; t++) {
                mx0 = fmaxf(mx0, fmaxf(s[t][0], s[t][1]));
                mx1 = fmaxf(mx1, fmaxf(s[t][2], s[t][3]));
            }
            mx0 = fmaxf(mx0, __shfl_xor_sync(0xffffffff, mx0, 1));
            mx0 = fmaxf(mx0, __shfl_xor_sync(0xffffffff, mx0, 2));
            mx1 = fmaxf(mx1, __shfl_xor_sync(0xffffffff, mx1, 1));
            mx1 = fmaxf(mx1, __shfl_xor_sync(0xffffffff, mx1, 2));

            float mn0 = fmaxf(m0, mx0), mn1 = fmaxf(m1, mx1);
            float al0 = __expf(m0 - mn0), al1 = __expf(m1 - mn1);
            m0 = mn0; m1 = mn1;

            float sum0 = 0.f, sum1 = 0.f;
            #pragma unroll
            for (int t = 0; t < 8; t++) {
                s[t][0] = __expf(s[t][0] - m0);
                s[t][1] = __expf(s[t][1] - m0);
                s[t][2] = __expf(s[t][2] - m1);
                s[t][3] = __expf(s[t][3] - m1);
                sum0 += s[t][0] + s[t][1];
                sum1 += s[t][2] + s[t][3];
            }
            sum0 += __shfl_xor_sync(0xffffffff, sum0, 1);
            sum0 += __shfl_xor_sync(0xffffffff, sum0, 2);
            sum1 += __shfl_xor_sync(0xffffffff, sum1, 1);
            sum1 += __shfl_xor_sync(0xffffffff, sum1, 2);
            l0 = l0 * al0 + sum0;
            l1 = l1 * al1 + sum1;

            #pragma unroll
            for (int t = 0; t < 12; t++) {
                o[t][0] *= al0; o[t][1] *= al0;
                o[t][2] *= al1; o[t][3] *= al1;
            }

            #pragma unroll
            for (int ks = 0; ks < 4; ks++) {
                const int j0 = 2*ks, j1 = 2*ks + 1;
                uint32_t ph[4];
                ph[0] = pack_f16x2(s[j0][0], s[j0][1]);
                ph[1] = pack_f16x2(s[j0][2], s[j0][3]);
                ph[2] = pack_f16x2(s[j1][0], s[j1][1]);
                ph[3] = pack_f16x2(s[j1][2], s[j1][3]);
                #pragma unroll
                for (int npp = 0; npp < 3; npp++) {
                    const int np = 2 * npp;
                    uint32_t voffa = (uint32_t)((ks*16 + vrow) * ALDS + np*16 + vn8) * 2;
                    uint32_t voffb = (uint32_t)((ks*16 + vrow) * ALDS + (np+1)*16 + vn8) * 2;
                    uint32_t vha[4], vhb[4];
                    ldsm4t(vha[0], vha[1], vha[2], vha[3], sV + voffa);
                    ldsm4t(vhb[0], vhb[1], vhb[2], vhb[3], sV + voffb);
                    mma16816h(o[2*np],   ph[0],ph[1],ph[2],ph[3], vha[0], vha[1]);
                    mma16816h(o[2*np+1], ph[0],ph[1],ph[2],ph[3], vha[2], vha[3]);
                    mma16816h(o[2*np+2], ph[0],ph[1],ph[2],ph[3], vhb[0], vhb[1]);
                    mma16816h(o[2*np+3], ph[0],ph[1],ph[2],ph[3], vhb[2], vhb[3]);
                }
            }
        }
        if (++bb == ASTAGES) bb = 0;
    }

    const float il0 = 1.f / l0, il1 = 1.f / l1;
    const size_t mrow0 = (size_t)(b * S_ + row_g0) * H_;
    const size_t mrow1 = mrow0 + 8 * (size_t)H_;
    #pragma unroll
    for (int t = 0; t < 12; t++) {
        int col = h * HD + t*8 + c2_;
        *(uint32_t*)(aout + mrow0 + col) = pack_f16x2(o[t][0]*il0, o[t][1]*il0);
        *(uint32_t*)(aout + mrow1 + col) = pack_f16x2(o[t][2]*il1, o[t][3]*il1);
    }
}

// ---------------------------------------------------------------------------

extern "C" void kernel_launch(void* const* d_in, const int* in_sizes, int n_in,
                              void* d_out, int out_size)
{
    const float* hidden = (const float*)d_in[0];
    const float* w_qkv  = (const float*)d_in[2];
    const float* w_o    = (const float*)d_in[3];
    float* out = (float*)d_out;

    float *qkv;
    __half *h_f16, *wq_f16, *wo_f16, *a_f16, *q_f16, *k_f16, *v_f16;
    cudaGetSymbolAddress((void**)&qkv,    g_qkv);
    cudaGetSymbolAddress((void**)&h_f16,  g_h_f16);
    cudaGetSymbolAddress((void**)&wq_f16, g_wq_f16);
    cudaGetSymbolAddress((void**)&wo_f16, g_wo_f16);
    cudaGetSymbolAddress((void**)&a_f16,  g_a_f16);
    cudaGetSymbolAddress((void**)&q_f16,  g_q_f16);
    cudaGetSymbolAddress((void**)&k_f16,  g_k_f16);
    cudaGetSymbolAddress((void**)&v_f16,  g_v_f16);

    cudaFuncSetAttribute(gemm_f16, cudaFuncAttributeMaxDynamicSharedMemorySize, GEMM_SMEM);
    cudaFuncSetAttribute(attn_mma, cudaFuncAttributeMaxDynamicSharedMemorySize, ATT_SMEM);

    // 1) round activations + weights to fp16
    {
        int n4;
        n4 = (M_ * H_) / 4;
        round_f16<<<(n4 + 255)/256, 256>>>(hidden, h_f16, n4);
        n4 = (QKV_W * H_) / 4;
        round_f16<<<(n4 + 255)/256, 256>>>(w_qkv, wq_f16, n4);
        n4 = (H_ * H_) / 4;
        round_f16<<<(n4 + 255)/256, 256>>>(w_o, wo_f16, n4);
    }

    // 2) QKV projection (1-pass fp16 HMMA)
    gemm_f16<<<dim3(QKV_W/128, M_/128), 256, GEMM_SMEM>>>(
        h_f16, wq_f16, qkv, QKV_W, H_);

    // 3) RoPE + rounds (attention operands, all single fp16 planes)
    {
        int total = B_ * S_ * (NH + NKV) * (HD/2);
        rope_split<<<(total + 255)/256, 256>>>(qkv, q_f16, k_f16);
        int vt = B_ * S_ * NKV * (HD/4);
        v_round<<<(vt + 255)/256, 256>>>(qkv, v_f16);
    }

    // 4) causal GQA flash attention (1-pass fp16, 2 CTAs/SM)
    attn_mma<<<dim3(S_/128, B_*NH), 256, ATT_SMEM>>>(
        q_f16, k_f16, v_f16, a_f16);

    // 5) output projection (1-pass fp16 HMMA)
    gemm_f16<<<dim3(H_/128, M_/128), 256, GEMM_SMEM>>>(
        a_f16, wo_f16, out, H_, H_);
}

// round 13
// speedup vs baseline: 2.6039x; 1.0001x over previous
#include <cuda_runtime.h>
#include <cuda_bf16.h>
#include <cuda_fp16.h>
#include <math.h>
#include <stdint.h>

#define B_   2
#define S_   2048
#define H_   3072
#define NH   32
#define NKV  8
#define HD   96
#define QKV_W (NH*HD + 2*NKV*HD)   // 4608
#define M_   (B_*S_)               // 4096

// ---------------- scratch (device globals: allocation-free rule) -----------
__device__ float g_qkv[(size_t)M_ * QKV_W];
__device__ __half g_h_f16[(size_t)M_ * H_];
__device__ __half g_wq_f16[(size_t)QKV_W * H_];
__device__ __half g_wo_f16[(size_t)H_ * H_];
__device__ __half g_a_f16[(size_t)M_ * H_];
__device__ __half g_q_f16[(size_t)B_*NH*S_*HD];
__device__ __half g_k_f16[(size_t)B_*NKV*S_*HD];
__device__ __half g_v_f16[(size_t)B_*NKV*S_*HD];

// ---------------- base-target PTX helpers ----------------------------------
__device__ __forceinline__ void cp_async16(uint32_t dst, const void* src) {
    asm volatile("cp.async.cg.shared.global [%0], [%1], 16;"
                 :: "r"(dst), "l"(src) : "memory");
}
#define CP_COMMIT() asm volatile("cp.async.commit_group;" ::: "memory")
#define CP_WAIT(n)  asm volatile("cp.async.wait_group %0;" :: "n"(n) : "memory")

__device__ __forceinline__ void ldsm4(uint32_t& r0, uint32_t& r1, uint32_t& r2,
                                      uint32_t& r3, uint32_t addr) {
    asm volatile("ldmatrix.sync.aligned.m8n8.x4.shared.b16 {%0,%1,%2,%3}, [%4];"
                 : "=r"(r0), "=r"(r1), "=r"(r2), "=r"(r3) : "r"(addr));
}
__device__ __forceinline__ void ldsm4t(uint32_t& r0, uint32_t& r1, uint32_t& r2,
                                       uint32_t& r3, uint32_t addr) {
    asm volatile("ldmatrix.sync.aligned.m8n8.x4.trans.shared.b16 {%0,%1,%2,%3}, [%4];"
                 : "=r"(r0), "=r"(r1), "=r"(r2), "=r"(r3) : "r"(addr));
}
__device__ __forceinline__ void mma16816h(float* c, uint32_t a0, uint32_t a1,
                                          uint32_t a2, uint32_t a3,
                                          uint32_t b0, uint32_t b1) {
    asm volatile(
        "mma.sync.aligned.m16n8k16.row.col.f32.f16.f16.f32 "
        "{%0,%1,%2,%3}, {%4,%5,%6,%7}, {%8,%9}, {%0,%1,%2,%3};"
        : "+f"(c[0]), "+f"(c[1]), "+f"(c[2]), "+f"(c[3])
        : "r"(a0), "r"(a1), "r"(a2), "r"(a3), "r"(b0), "r"(b1));
}

__device__ __forceinline__ uint32_t pack_f16x2(float lo, float hi) {
    __half2 p = __floats2half2_rn(lo, hi);
    return *(uint32_t*)&p;
}

// ---------------------------------------------------------------------------
// fp32 -> fp16 round
// ---------------------------------------------------------------------------
__global__ void round_f16(const float* __restrict__ x, __half* __restrict__ h, int n4)
{
    int i = blockIdx.x * blockDim.x + threadIdx.x;
    if (i >= n4) return;
    float4 v = ((const float4*)x)[i];
    ((__half2*)h)[2*i]   = __floats2half2_rn(v.x, v.y);
    ((__half2*)h)[2*i+1] = __floats2half2_rn(v.z, v.w);
}

// ---------------------------------------------------------------------------
// 1-pass fp16 mma.sync GEMM (NT). 128x128 CTA tile, BK=64, 3-stage ring,
// 2 CTAs/SM, CP_WAIT(1) keeps one chunk in flight through compute.
// ---------------------------------------------------------------------------
#define BK      64
#define LDS_    72
#define PLANE_B (128 * LDS_ * 2)      // 18432
#define BUF_B   (2 * PLANE_B)         // 36864
#define GSTAGES 3
#define GEMM_SMEM (GSTAGES * BUF_B)   // 110592 -> 2 CTAs/SM

__global__ __launch_bounds__(256, 2) void gemm_f16(
    const __half* __restrict__ A, const __half* __restrict__ Bw,
    float* __restrict__ C, int N, int K)
{
    extern __shared__ __align__(128) char smc[];
    const uint32_t sbase = (uint32_t)__cvta_generic_to_shared(smc);
    const int tid  = threadIdx.x;
    const int warp = tid >> 5, lane = tid & 31;
    const int bm = blockIdx.y * 128, bn = blockIdx.x * 128;
    const int wm = (warp >> 2) * 64;
    const int wn = (warp & 3) * 32;

    const __half* srcs[2] = { A + (size_t)bm * K, Bw + (size_t)bn * K };

    const int nch = K / BK;

    auto load_chunk = [&](int kc, int bb) {
        uint32_t sb = sbase + bb * BUF_B;
        #pragma unroll
        for (int p = 0; p < 2; p++) {
            const __half* sp = srcs[p] + kc * BK;
            uint32_t pb = sb + p * PLANE_B;
            #pragma unroll
            for (int t = 0; t < 4; t++) {
                int f = tid + t * 256;
                int r = f >> 3, j = f & 7;
                cp_async16(pb + r * (LDS_ * 2) + j * 16,
                           sp + (size_t)r * K + j * 8);
            }
        }
        CP_COMMIT();
    };

    float c[4][4][4];
    #pragma unroll
    for (int i = 0; i < 4; i++)
        #pragma unroll
        for (int j = 0; j < 4; j++)
            #pragma unroll
            for (int q = 0; q < 4; q++) c[i][j][q] = 0.f;

    load_chunk(0, 0);
    load_chunk(1, 1);

    const int arow = lane & 15;
    const int ak8  = (lane >> 4) * 8;
    const int brow = (lane & 7) + ((lane >> 4) << 3);
    const int bk8  = ((lane >> 3) & 1) * 8;

    int bb = 0;
    #pragma unroll 1
    for (int kc = 0; kc < nch; kc++) {
        CP_WAIT(1);                 // chunk kc resident; kc+1 may stay in flight
        __syncthreads();            // all warps done reading the buffer reloaded next
        if (kc + 2 < nch) {
            int nb = bb + 2; if (nb >= GSTAGES) nb -= GSTAGES;
            load_chunk(kc + 2, nb);
        } else CP_COMMIT();         // keep group-count invariant for CP_WAIT(1)

        const uint32_t sA = sbase + bb * BUF_B;
        const uint32_t sB = sA + PLANE_B;

        #pragma unroll
        for (int ks = 0; ks < 4; ks++) {
            const int k0 = ks * 16;
            uint32_t bh[4][2];
            #pragma unroll
            for (int tp = 0; tp < 2; tp++) {
                uint32_t off = (uint32_t)((wn + tp*16 + brow) * LDS_ + k0 + bk8) * 2;
                ldsm4(bh[tp*2][0], bh[tp*2][1], bh[tp*2+1][0], bh[tp*2+1][1], sB + off);
            }
            #pragma unroll
            for (int ti = 0; ti < 4; ti++) {
                uint32_t off = (uint32_t)((wm + ti*16 + arow) * LDS_ + k0 + ak8) * 2;
                uint32_t ah[4];
                ldsm4(ah[0], ah[1], ah[2], ah[3], sA + off);
                mma16816h(c[ti][0], ah[0], ah[1], ah[2], ah[3], bh[0][0], bh[0][1]);
                mma16816h(c[ti][1], ah[0], ah[1], ah[2], ah[3], bh[1][0], bh[1][1]);
                mma16816h(c[ti][2], ah[0], ah[1], ah[2], ah[3], bh[2][0], bh[2][1]);
                mma16816h(c[ti][3], ah[0], ah[1], ah[2], ah[3], bh[3][0], bh[3][1]);
            }
        }
        if (++bb == GSTAGES) bb = 0;
    }

    const int cr = lane >> 2, cc = (lane & 3) * 2;
    #pragma unroll
    for (int ti = 0; ti < 4; ti++) {
        #pragma unroll
        for (int tj = 0; tj < 4; tj++) {
            int r0 = bm + wm + ti*16 + cr;
            int col = bn + wn + tj*8 + cc;
            *(float2*)(C + (size_t)r0 * N + col)       = make_float2(c[ti][tj][0], c[ti][tj][1]);
            *(float2*)(C + (size_t)(r0 + 8) * N + col) = make_float2(c[ti][tj][2], c[ti][tj][3]);
        }
    }
}

// ---------------------------------------------------------------------------
// RoPE: Q -> fp16 plane (scale folded), K -> fp16 plane.
// ---------------------------------------------------------------------------
__global__ void rope_split(const float* __restrict__ qkv,
                           __half* __restrict__ qf, __half* __restrict__ kf)
{
    const int total = B_ * S_ * (NH + NKV) * (HD / 2);
    int i = blockIdx.x * blockDim.x + threadIdx.x;
    if (i >= total) return;
    int d    = i % (HD/2);
    int t    = i / (HD/2);
    int head = t % (NH + NKV);
    int bs   = t / (NH + NKV);
    int b    = bs / S_;
    int s    = bs % S_;

    float inv = expf(-(float)d * (logf(10000.0f) / 48.0f));
    float ang = (float)s * inv;
    float sn, cs;
    sincosf(ang, &sn, &cs);

    const float* base = qkv + (size_t)bs * QKV_W + head * HD;
    float x1 = base[d];
    float x2 = base[d + 48];
    float y1 = x1 * cs - x2 * sn;
    float y2 = x2 * cs + x1 * sn;

    if (head < NH) {
        const float scale = 0.10206207261596577f;
        y1 *= scale; y2 *= scale;
        size_t idx = ((size_t)(b * NH + head) * S_ + s) * HD;
        qf[idx + d]      = __float2half_rn(y1);
        qf[idx + d + 48] = __float2half_rn(y2);
    } else {
        size_t idx = ((size_t)(b * NKV + (head - NH)) * S_ + s) * HD;
        kf[idx + d]      = __float2half_rn(y1);
        kf[idx + d + 48] = __float2half_rn(y2);
    }
}

// V: round to head-major fp16 plane.
__global__ void v_round(const float* __restrict__ qkv, __half* __restrict__ vf)
{
    const int total = B_ * S_ * NKV * (HD / 4);
    int i = blockIdx.x * blockDim.x + threadIdx.x;
    if (i >= total) return;
    int d4  = i % (HD/4);
    int t   = i / (HD/4);
    int kvh = t % NKV;
    int bs  = t / NKV;
    int b   = bs / S_;
    int s   = bs % S_;

    const float* src = qkv + (size_t)bs * QKV_W + NH*HD + NKV*HD + kvh*HD + d4*4;
    float4 v = *(const float4*)src;
    size_t idx = ((size_t)(b * NKV + kvh) * S_ + s) * HD + d4*4;
    *(__half2*)(vf + idx)     = __floats2half2_rn(v.x, v.y);
    *(__half2*)(vf + idx + 2) = __floats2half2_rn(v.z, v.w);
}

// ---------------------------------------------------------------------------
// Flash attention, 1-pass fp16 mma. CTA: 128 queries x one (b,h).
// 8 warps x 16 rows, 64-key tiles, 3-stage 2-plane KV ring, 2 CTAs/SM.
// q-tiles reversed: heaviest causal tiles launch first (tail trim).
// ---------------------------------------------------------------------------
#define ALDS   104
#define QBYTES (128 * ALDS * 2)         // 26624
#define KVTILE (64 * ALDS * 2)          // 13312
#define KVBUF  (2 * KVTILE)             // 26624
#define ASTAGES 3
#define ATT_SMEM (QBYTES + ASTAGES*KVBUF)   // 106496 -> 2 CTAs/SM

__global__ __launch_bounds__(256, 2) void attn_mma(
    const __half* __restrict__ qf, const __half* __restrict__ kf,
    const __half* __restrict__ vf, __half* __restrict__ aout)
{
    extern __shared__ __align__(128) char smc[];
    const uint32_t sb  = (uint32_t)__cvta_generic_to_shared(smc);
    const uint32_t sQ  = sb;
    const uint32_t sKV = sb + QBYTES;

    const int tid  = threadIdx.x;
    const int warp = tid >> 5, lane = tid & 31;
    const int qt = (S_/128 - 1) - blockIdx.x;   // reversed: heavy tiles first
    const int bh = blockIdx.y;
    const int b  = bh >> 5, h = bh & 31, kvh = h >> 2;
    const int q0 = qt * 128;
    const int wm = warp * 16;

    const __half* qsf = qf + ((size_t)(b*NH + h) * S_ + q0) * HD;
    const __half* ksf = kf + (size_t)(b*NKV + kvh) * S_ * HD;
    const __half* vsf = vf + (size_t)(b*NKV + kvh) * S_ * HD;

    #pragma unroll
    for (int u = 0; u < 6; u++) {
        int f = tid + u * 256;
        int r = f / 12, cidx = f % 12;
        cp_async16(sQ + r * (ALDS*2) + cidx * 16, qsf + (size_t)r * HD + cidx * 8);
    }

    auto load_kv = [&](int kt, int bb) {
        uint32_t base = sKV + bb * KVBUF;
        int k0 = kt * 64;
        #pragma unroll
        for (int u = 0; u < 3; u++) {
            int f = tid + u * 256;
            int r = f / 12, cidx = f % 12;
            size_t g = (size_t)(k0 + r) * HD + cidx * 8;
            uint32_t o = r * (ALDS*2) + cidx * 16;
            cp_async16(base + 0*KVTILE + o, ksf + g);
            cp_async16(base + 1*KVTILE + o, vsf + g);
        }
        CP_COMMIT();
    };

    const int nkt = 2 * qt + 2;
    load_kv(0, 0);
    if (nkt > 1) load_kv(1, 1); else CP_COMMIT();

    const int arow = lane & 15;
    const int ak8  = (lane >> 4) * 8;
    const int brow = (lane & 7) + ((lane >> 4) << 3);
    const int bk8  = ((lane >> 3) & 1) * 8;
    const int vrow = lane & 15;
    const int vn8  = (lane >> 4) * 8;
    const int r_   = lane >> 2;
    const int c2_  = (lane & 3) * 2;

    float o[12][4];
    #pragma unroll
    for (int t = 0; t < 12; t++)
        #pragma unroll
        for (int q = 0; q < 4; q++) o[t][q] = 0.f;
    float m0 = -1e30f, m1 = -1e30f, l0 = 0.f, l1 = 0.f;

    const int row_g0 = q0 + wm + r_;
    const int wmax   = q0 + wm + 15;

    int bb = 0;
    #pragma unroll 1
    for (int kt = 0; kt < nkt; kt++) {
        const int k0 = kt * 64;
        CP_WAIT(1);
        __syncthreads();
        if (kt + 2 < nkt) {
            int nb = bb + 2; if (nb >= ASTAGES) nb -= ASTAGES;
            load_kv(kt + 2, nb);
        } else CP_COMMIT();

        if (k0 <= wmax) {
            const uint32_t sK = sKV + bb * KVBUF;
            const uint32_t sV = sK + KVTILE;

            float s[8][4];
            #pragma unroll
            for (int t = 0; t < 8; t++)
                #pragma unroll
                for (int q = 0; q < 4; q++) s[t][q] = 0.f;

            #pragma unroll
            for (int ks = 0; ks < 6; ks++) {
                uint32_t aoff = (uint32_t)((wm + arow) * ALDS + ks*16 + ak8) * 2;
                uint32_t ah[4];
                ldsm4(ah[0], ah[1], ah[2], ah[3], sQ + aoff);
                #pragma unroll
                for (int np = 0; np < 4; np++) {
                    uint32_t boff = (uint32_t)((np*16 + brow) * ALDS + ks*16 + bk8) * 2;
                    uint32_t kh_[4];
                    ldsm4(kh_[0], kh_[1], kh_[2], kh_[3], sK + boff);
                    mma16816h(s[2*np],   ah[0],ah[1],ah[2],ah[3], kh_[0], kh_[1]);
                    mma16816h(s[2*np+1], ah[0],ah[1],ah[2],ah[3], kh_[2], kh_[3]);
                }
            }

            if (k0 + 63 > q0 + wm) {
                #pragma unroll
                for (int t = 0; t < 8; t++) {
                    int col = k0 + t*8 + c2_;
                    if (col     > row_g0)     s[t][0] = -1e30f;
                    if (col + 1 > row_g0)     s[t][1] = -1e30f;
                    if (col     > row_g0 + 8) s[t][2] = -1e30f;
                    if (col + 1 > row_g0 + 8) s[t][3] = -1e30f;
                }
            }

            float mx0 = -1e30f, mx1 = -1e30f;
            #pragma unroll
            for (int t = 0; t < 8; t++) {
                mx0 = fmaxf(mx0, fmaxf(s[t][0], s[t][1]));
                mx1 = fmaxf(mx1, fmaxf(s[t][2], s[t][3]));
            }
            mx0 = fmaxf(mx0, __shfl_xor_sync(0xffffffff, mx0, 1));
            mx0 = fmaxf(mx0, __shfl_xor_sync(0xffffffff, mx0, 2));
            mx1 = fmaxf(mx1, __shfl_xor_sync(0xffffffff, mx1, 1));
            mx1 = fmaxf(mx1, __shfl_xor_sync(0xffffffff, mx1, 2));

            float mn0 = fmaxf(m0, mx0), mn1 = fmaxf(m1, mx1);
            float al0 = __expf(m0 - mn0), al1 = __expf(m1 - mn1);
            m0 = mn0; m1 = mn1;

            float sum0 = 0.f, sum1 = 0.f;
            #pragma unroll
            for (int t = 0; t < 8; t++) {
                s[t][0] = __expf(s[t][0] - m0);
                s[t][1] = __expf(s[t][1] - m0);
                s[t][2] = __expf(s[t][2] - m1);
                s[t][3] = __expf(s[t][3] - m1);
                sum0 += s[t][0] + s[t][1];
                sum1 += s[t][2] + s[t][3];
            }
            sum0 += __shfl_xor_sync(0xffffffff, sum0, 1);
            sum0 += __shfl_xor_sync(0xffffffff, sum0, 2);
            sum1 += __shfl_xor_sync(0xffffffff, sum1, 1);
            sum1 += __shfl_xor_sync(0xffffffff, sum1, 2);
            l0 = l0 * al0 + sum0;
            l1 = l1 * al1 + sum1;

            #pragma unroll
            for (int t = 0; t < 12; t++) {
                o[t][0] *= al0; o[t][1] *= al0;
                o[t][2] *= al1; o[t][3] *= al1;
            }

            #pragma unroll
            for (int ks = 0; ks < 4; ks++) {
                const int j0 = 2*ks, j1 = 2*ks + 1;
                uint32_t ph[4];
                ph[0] = pack_f16x2(s[j0][0], s[j0][1]);
                ph[1] = pack_f16x2(s[j0][2], s[j0][3]);
                ph[2] = pack_f16x2(s[j1][0], s[j1][1]);
                ph[3] = pack_f16x2(s[j1][2], s[j1][3]);
                #pragma unroll
                for (int npp = 0; npp < 3; npp++) {
                    const int np = 2 * npp;
                    uint32_t voffa = (uint32_t)((ks*16 + vrow) * ALDS + np*16 + vn8) * 2;
                    uint32_t voffb = (uint32_t)((ks*16 + vrow) * ALDS + (np+1)*16 + vn8) * 2;
                    uint32_t vha[4], vhb[4];
                    ldsm4t(vha[0], vha[1], vha[2], vha[3], sV + voffa);
                    ldsm4t(vhb[0], vhb[1], vhb[2], vhb[3], sV + voffb);
                    mma16816h(o[2*np],   ph[0],ph[1],ph[2],ph[3], vha[0], vha[1]);
                    mma16816h(o[2*np+1], ph[0],ph[1],ph[2],ph[3], vha[2], vha[3]);
                    mma16816h(o[2*np+2], ph[0],ph[1],ph[2],ph[3], vhb[0], vhb[1]);
                    mma16816h(o[2*np+3], ph[0],ph[1],ph[2],ph[3], vhb[2], vhb[3]);
                }
            }
        }
        if (++bb == ASTAGES) bb = 0;
    }

    const float il0 = 1.f / l0, il1 = 1.f / l1;
    const size_t mrow0 = (size_t)(b * S_ + row_g0) * H_;
    const size_t mrow1 = mrow0 + 8 * (size_t)H_;
    #pragma unroll
    for (int t = 0; t < 12; t++) {
        int col = h * HD + t*8 + c2_;
        *(uint32_t*)(aout + mrow0 + col) = pack_f16x2(o[t][0]*il0, o[t][1]*il0);
        *(uint32_t*)(aout + mrow1 + col) = pack_f16x2(o[t][2]*il1, o[t][3]*il1);
    }
}

// ---------------------------------------------------------------------------

extern "C" void kernel_launch(void* const* d_in, const int* in_sizes, int n_in,
                              void* d_out, int out_size)
{
    const float* hidden = (const float*)d_in[0];
    const float* w_qkv  = (const float*)d_in[2];
    const float* w_o    = (const float*)d_in[3];
    float* out = (float*)d_out;

    float *qkv;
    __half *h_f16, *wq_f16, *wo_f16, *a_f16, *q_f16, *k_f16, *v_f16;
    cudaGetSymbolAddress((void**)&qkv,    g_qkv);
    cudaGetSymbolAddress((void**)&h_f16,  g_h_f16);
    cudaGetSymbolAddress((void**)&wq_f16, g_wq_f16);
    cudaGetSymbolAddress((void**)&wo_f16, g_wo_f16);
    cudaGetSymbolAddress((void**)&a_f16,  g_a_f16);
    cudaGetSymbolAddress((void**)&q_f16,  g_q_f16);
    cudaGetSymbolAddress((void**)&k_f16,  g_k_f16);
    cudaGetSymbolAddress((void**)&v_f16,  g_v_f16);

    cudaFuncSetAttribute(gemm_f16, cudaFuncAttributeMaxDynamicSharedMemorySize, GEMM_SMEM);
    cudaFuncSetAttribute(attn_mma, cudaFuncAttributeMaxDynamicSharedMemorySize, ATT_SMEM);

    {
        int n4;
        n4 = (M_ * H_) / 4;
        round_f16<<<(n4 + 255)/256, 256>>>(hidden, h_f16, n4);
        n4 = (QKV_W * H_) / 4;
        round_f16<<<(n4 + 255)/256, 256>>>(w_qkv, wq_f16, n4);
        n4 = (H_ * H_) / 4;
        round_f16<<<(n4 + 255)/256, 256>>>(w_o, wo_f16, n4);
    }

    gemm_f16<<<dim3(QKV_W/128, M_/128), 256, GEMM_SMEM>>>(
        h_f16, wq_f16, qkv, QKV_W, H_);

    {
        int total = B_ * S_ * (NH + NKV) * (HD/2);
        rope_split<<<(total + 255)/256, 256>>>(qkv, q_f16, k_f16);
        int vt = B_ * S_ * NKV * (HD/4);
        v_round<<<(vt + 255)/256, 256>>>(qkv, v_f16);
    }

    attn_mma<<<dim3(S_/128, B_*NH), 256, ATT_SMEM>>>(
        q_f16, k_f16, v_f16, a_f16);

    gemm_f16<<<dim3(H_/128, M_/128), 256, GEMM_SMEM>>>(
        a_f16, wo_f16, out, H_, H_);
}